// round 14
// baseline (speedup 1.0000x reference)
#include <cuda_runtime.h>
#include <cuda_fp16.h>
#include <math.h>
#include <stdint.h>

#define NB     16
#define SS     512
#define HH     1024
#define H3     (3*HH)
#define VV     8000
#define VPAD   8064
#define LLAY   8
#define NHEADS 4
#define DHEAD  256
#define NTOK   (NB*SS)

typedef __half  f16;
typedef __half2 f162;

// ---------------- scratch (__device__ globals) --------------------------------
__device__ float g_s  [NB*NHEADS*SS*SS];          // attention scores fp32
__device__ f16 g_zh  [NTOK*HH],  g_zl [NTOK*HH];  // residual stream pairs
__device__ f16 g_z1h [NTOK*HH],  g_z1l[NTOK*HH];
__device__ f16 g_qkvh[NTOK*H3],  g_qkvl[NTOK*H3];
__device__ f16 g_fh  [NTOK*HH];                   // FFN1 out (hi only)
__device__ f16 g_och [NTOK*HH],  g_ocl[NTOK*HH];  // fused (residual+out) pairs
__device__ f16 g_ph  [NB*NHEADS*SS*SS];           // P hi only
__device__ f16 g_vth [NTOK*HH];                   // V^T [bh][dh][S]
__device__ f16 g_Wqkvh[LLAY*H3*HH];
__device__ f16 g_W1h[LLAY*HH*HH];
__device__ f16 g_W2h[LLAY*HH*HH];
__device__ f16 g_Wfh[HH*HH];
__device__ f16 g_emh[VPAD*HH];
__device__ float g_bqkv[LLAY*H3];

// ---------------- helpers -----------------------------------------------------
__device__ __forceinline__ void hsplit(float x, f16& h, f16& l){
    h = __float2half(x);
    l = __float2half(x - __half2float(h));
}
__device__ __forceinline__ void mma_f16(float* c, const uint32_t* a, const uint32_t* b){
    asm volatile("mma.sync.aligned.m16n8k16.row.col.f32.f16.f16.f32 "
        "{%0,%1,%2,%3}, {%4,%5,%6,%7}, {%8,%9}, {%0,%1,%2,%3};"
        : "+f"(c[0]),"+f"(c[1]),"+f"(c[2]),"+f"(c[3])
        : "r"(a[0]),"r"(a[1]),"r"(a[2]),"r"(a[3]), "r"(b[0]),"r"(b[1]));
}
__device__ __forceinline__ void ldsm4(uint32_t* r, uint32_t addr){
    asm volatile("ldmatrix.sync.aligned.m8n8.x4.shared.b16 {%0,%1,%2,%3}, [%4];"
        : "=r"(r[0]),"=r"(r[1]),"=r"(r[2]),"=r"(r[3]) : "r"(addr));
}
__device__ __forceinline__ uint32_t s2u(const void* p){
    uint32_t a;
    asm("{ .reg .u64 t; cvta.to.shared.u64 t, %1; cvt.u32.u64 %0, t; }" : "=r"(a) : "l"(p));
    return a;
}
__device__ __forceinline__ void cp16(uint32_t dst, const void* src){
    asm volatile("cp.async.cg.shared.global [%0], [%1], 16;" :: "r"(dst), "l"(src));
}

// ================= fp16 NT GEMM: ldmatrix, cp.async 4-stage ===================
// SPLITA=2: A = Ah+Al; SPLITA=1: A hi only. RES=1: add residual pairs (same
// flat offsets as output) in epilogue before split-store.
// causal!=0: skip tiles n0 > m0+127.  triK!=0: effective K = m0+128.
template<int EPI, int SPLITA, int RES>
__global__ void __launch_bounds__(256,2) tgemm(
    const f16* __restrict__ Ah, const f16* __restrict__ Al,
    const f16* __restrict__ Bh,
    const float* __restrict__ bias,
    const f16* __restrict__ Resh, const f16* __restrict__ Resl,
    float* __restrict__ C, f16* __restrict__ Ch, f16* __restrict__ Cl,
    int M, int N, int K, int lda, int ldb, int ldc, float alpha, int Nst,
    int causal, int triK,
    int divz, long long sA1, long long sA2, long long sB1, long long sB2,
    long long sC1, long long sC2)
{
    constexpr uint32_t STGB = (SPLITA==2) ? 24576u : 16384u;
    constexpr uint32_t BOFF = (SPLITA==2) ? 16384u : 8192u;
    extern __shared__ char smem[];
    const int m0 = blockIdx.y*128, n0 = blockIdx.x*128;
    if (causal && n0 > m0 + 127) return;

    const int z = blockIdx.z;
    const long long offA = (long long)(z/divz)*sA1 + (long long)(z%divz)*sA2;
    const long long offB = (long long)(z/divz)*sB1 + (long long)(z%divz)*sB2;
    const long long offC = (long long)(z/divz)*sC1 + (long long)(z%divz)*sC2;
    Ah += offA; Al += offA; Bh += offB;

    const int tid = threadIdx.x;
    const int wid = tid>>5, lane = tid&31;
    const int g = lane>>2, t = lane&3;
    const int m0w = (wid&1)*64, n0w = (wid>>1)*32;

    const int a_ro = ((lane>>3)&1)*8 + (lane&7);
    const int a_kh = lane>>4;
    const int a_sw = (a_ro>>1)&3;
    const int b_ro = (lane>>4)*8 + (lane&7);
    const int b_kh = (lane>>3)&1;
    const int b_sw = (b_ro>>1)&3;

    const uint32_t sb = s2u(smem);
    const int srow = tid>>2;
    const int sch  = tid&3;
    const uint32_t soff0 = (uint32_t)(srow*64 + ((sch  ^ ((srow>>1)&3))<<4));
    const int srow1 = (tid+256)>>2;
    const uint32_t soff1 = (uint32_t)(srow1*64 + ((sch ^ ((srow1>>1)&3))<<4));

    float acc[4][4][4];
#pragma unroll
    for (int i=0;i<4;i++)
#pragma unroll
        for (int j=0;j<4;j++)
#pragma unroll
            for (int r=0;r<4;r++) acc[i][j][r]=0.f;

    const int Keff = triK ? (m0 + 128) : K;
    const int nch = Keff >> 5;

    auto stage_chunk = [&](int c, int st){
        const uint32_t base = sb + (uint32_t)st*STGB;
        const int kc = c*32;
        {
            const long long ga = (long long)(m0+srow)*lda + kc + sch*8;
            const long long gb = (long long)(n0+srow)*ldb + kc + sch*8;
            cp16(base +        soff0, Ah + ga);
            if (SPLITA==2) cp16(base + 8192 + soff0, Al + ga);
            cp16(base + BOFF + soff0, Bh + gb);
        }
        {
            const long long ga = (long long)(m0+srow1)*lda + kc + sch*8;
            const long long gb = (long long)(n0+srow1)*ldb + kc + sch*8;
            cp16(base +        soff1, Ah + ga);
            if (SPLITA==2) cp16(base + 8192 + soff1, Al + ga);
            cp16(base + BOFF + soff1, Bh + gb);
        }
        asm volatile("cp.async.commit_group;");
    };

    stage_chunk(0,0);
    stage_chunk(1,1);
    stage_chunk(2,2);

    for (int c=0; c<nch; c++){
        const int st = c & 3;
        if      (c+2 < nch) asm volatile("cp.async.wait_group 2;");
        else if (c+1 < nch) asm volatile("cp.async.wait_group 1;");
        else                asm volatile("cp.async.wait_group 0;");
        __syncthreads();
        if (c+3 < nch) stage_chunk(c+3, (c+3)&3);

        const uint32_t base = sb + (uint32_t)st*STGB;
#pragma unroll
        for (int ks=0; ks<2; ks++){
            uint32_t bh[4][2];
#pragma unroll
            for (int jp=0; jp<2; jp++){
                uint32_t r4[4];
                const uint32_t addrB = base + BOFF
                    + (uint32_t)(n0w + jp*16 + b_ro)*64u
                    + (uint32_t)(((ks*2 + b_kh) ^ b_sw)<<4);
                ldsm4(r4, addrB);
                bh[2*jp  ][0] = r4[0]; bh[2*jp  ][1] = r4[1];
                bh[2*jp+1][0] = r4[2]; bh[2*jp+1][1] = r4[3];
            }
#pragma unroll
            for (int i=0;i<4;i++){
                const uint32_t addrA = base
                    + (uint32_t)(m0w + i*16 + a_ro)*64u
                    + (uint32_t)(((ks*2 + a_kh) ^ a_sw)<<4);
                uint32_t ah[4];
                ldsm4(ah, addrA);
                uint32_t al[4];
                if (SPLITA==2) ldsm4(al, addrA + 8192u);
#pragma unroll
                for (int j=0;j<4;j++){
                    mma_f16(acc[i][j], ah, bh[j]);
                    if (SPLITA==2) mma_f16(acc[i][j], al, bh[j]);
                }
            }
        }
    }

    // ---- epilogue ----
#pragma unroll
    for (int i=0;i<4;i++){
        const long long r0 = m0 + m0w + i*16 + g;
        const long long r1 = r0 + 8;
#pragma unroll
        for (int j=0;j<4;j++){
            const int col = n0 + n0w + j*8 + 2*t;
            if (col < Nst){
                float b0=0.f, b1=0.f;
                if (bias){ b0 = bias[col]; b1 = bias[col+1]; }
                float c0 = acc[i][j][0]*alpha + b0;
                float c1 = acc[i][j][1]*alpha + b1;
                float c2 = acc[i][j][2]*alpha + b0;
                float c3 = acc[i][j][3]*alpha + b1;
                if (EPI==1){
                    c0 = 0.5f*c0*(1.0f+erff(c0*0.70710678118654752440f));
                    c1 = 0.5f*c1*(1.0f+erff(c1*0.70710678118654752440f));
                    c2 = 0.5f*c2*(1.0f+erff(c2*0.70710678118654752440f));
                    c3 = 0.5f*c3*(1.0f+erff(c3*0.70710678118654752440f));
                }
                if (RES){
                    const long long p0 = offC + r0*ldc + col;
                    const long long p1 = offC + r1*ldc + col;
                    f162 rh0 = *(const f162*)&Resh[p0], rl0 = *(const f162*)&Resl[p0];
                    f162 rh1 = *(const f162*)&Resh[p1], rl1 = *(const f162*)&Resl[p1];
                    c0 += __half2float(rh0.x) + __half2float(rl0.x);
                    c1 += __half2float(rh0.y) + __half2float(rl0.y);
                    c2 += __half2float(rh1.x) + __half2float(rl1.x);
                    c3 += __half2float(rh1.y) + __half2float(rl1.y);
                }
                if (C){
                    *(float2*)&C[(offC + r0*ldc) + col] = make_float2(c0,c1);
                    *(float2*)&C[(offC + r1*ldc) + col] = make_float2(c2,c3);
                }
                if (Ch){
                    if (Cl){
                        f162 h0,l0,h1,l1;
                        hsplit(c0,h0.x,l0.x); hsplit(c1,h0.y,l0.y);
                        hsplit(c2,h1.x,l1.x); hsplit(c3,h1.y,l1.y);
                        *(f162*)&Ch[(offC + r0*ldc) + col] = h0;
                        *(f162*)&Cl[(offC + r0*ldc) + col] = l0;
                        *(f162*)&Ch[(offC + r1*ldc) + col] = h1;
                        *(f162*)&Cl[(offC + r1*ldc) + col] = l1;
                    } else {
                        *(f162*)&Ch[(offC + r0*ldc) + col] = __floats2half2_rn(c0,c1);
                        *(f162*)&Ch[(offC + r1*ldc) + col] = __floats2half2_rn(c2,c3);
                    }
                }
            }
        }
    }
}

// ---------------- weight rounding -------------------------------------------
__global__ __launch_bounds__(256) void round_kernel(
    const float* __restrict__ in, f16* __restrict__ h, int n)
{
    int i = (blockIdx.x*256 + threadIdx.x)*4;
    if (i < n){
        float4 v = *(const float4*)&in[i];
        *(f162*)&h[i]   = __floats2half2_rn(v.x, v.y);
        *(f162*)&h[i+2] = __floats2half2_rn(v.z, v.w);
    }
}
__global__ __launch_bounds__(256) void round_qkv_kernel(
    const float* __restrict__ in, f16* __restrict__ out, int part)
{
    int i = (blockIdx.x*256 + threadIdx.x)*4;
    int l = i / (HH*HH), r = i % (HH*HH);
    long long o = (long long)l*H3*HH + (long long)part*HH*HH + r;
    float4 v = *(const float4*)&in[i];
    *(f162*)&out[o]   = __floats2half2_rn(v.x, v.y);
    *(f162*)&out[o+2] = __floats2half2_rn(v.z, v.w);
}
__global__ __launch_bounds__(256) void bias_concat_kernel(
    const float* __restrict__ bq, const float* __restrict__ bk,
    const float* __restrict__ bv, float* __restrict__ o)
{
    int i = blockIdx.x*256 + threadIdx.x;
    int l = i/HH, c = i%HH;
    o[(long long)l*H3 + c]        = bq[i];
    o[(long long)l*H3 + HH + c]   = bk[i];
    o[(long long)l*H3 + 2*HH + c] = bv[i];
}
__global__ __launch_bounds__(256) void emb_round_pad_kernel(
    const float* __restrict__ emb, f16* __restrict__ h)
{
    int i = (blockIdx.x*256 + threadIdx.x)*4;
    int row = i >> 10;
    float4 v = make_float4(0.f,0.f,0.f,0.f);
    if (row < VV) v = *(const float4*)&emb[(long long)row*HH + (i & 1023)];
    *(f162*)&h[i]   = __floats2half2_rn(v.x, v.y);
    *(f162*)&h[i+2] = __floats2half2_rn(v.z, v.w);
}

// ---------------- V transpose from qkv slice ---------------------------------
__global__ __launch_bounds__(256) void transpose_v_f16(
    const f16* __restrict__ V, f16* __restrict__ Vth)
{
    __shared__ float tbuf[32][33];
    const int bh = blockIdx.z, b = bh >> 2, h = bh & 3;
    const int s0 = blockIdx.x*32, d0 = blockIdx.y*32;
    const int tx = threadIdx.x & 31, ty = threadIdx.x >> 5;
#pragma unroll
    for (int i=0;i<4;i++){
        int r = ty + i*8;
        tbuf[r][tx] = __half2float(V[(long long)(b*SS + s0 + r)*H3 + h*DHEAD + d0 + tx]);
    }
    __syncthreads();
#pragma unroll
    for (int i=0;i<4;i++){
        int r = ty + i*8;
        Vth[(long long)(bh*DHEAD + d0 + r)*SS + s0 + tx] = __float2half(tbuf[tx][r]);
    }
}

// ---------------- reductions -------------------------------------------------
__device__ __forceinline__ float warp_sum(float v){
#pragma unroll
    for(int o=16;o;o>>=1) v += __shfl_xor_sync(0xffffffffu,v,o);
    return v;
}
__device__ __forceinline__ float warp_max(float v){
#pragma unroll
    for(int o=16;o;o>>=1) v = fmaxf(v,__shfl_xor_sync(0xffffffffu,v,o));
    return v;
}
template<int NW>
__device__ __forceinline__ float block_sum(float v, float* sh){
    v = warp_sum(v);
    if((threadIdx.x&31)==0) sh[threadIdx.x>>5]=v;
    __syncthreads();
    float t=0.f;
#pragma unroll
    for(int i=0;i<NW;i++) t+=sh[i];
    __syncthreads();
    return t;
}
template<int NW>
__device__ __forceinline__ float block_max(float v, float* sh){
    v = warp_max(v);
    if((threadIdx.x&31)==0) sh[threadIdx.x>>5]=v;
    __syncthreads();
    float t=-1e30f;
#pragma unroll
    for(int i=0;i<NW;i++) t=fmaxf(t,sh[i]);
    __syncthreads();
    return t;
}

// ---------------- embedding + PE -> f16 pairs --------------------------------
__global__ __launch_bounds__(256) void embed_kernel(
    const int* __restrict__ x, const float* __restrict__ emb,
    f16* __restrict__ zh, f16* __restrict__ zl)
{
    const int row = blockIdx.x;
    const int s = row & (SS-1);
    const int tok = x[row];
    const int c0 = threadIdx.x*4;
    float4 ev = *(const float4*)&emb[(long long)tok*HH + c0];
    float vv[4] = {ev.x, ev.y, ev.z, ev.w};
#pragma unroll
    for(int i=0;i<4;i++){
        int c = c0 + i;
        int half = c >> 1;
        float dv = expf(-(float)(2*half) * (9.210340371976184f/(float)HH));
        float ang = (float)s * dv;
        float pe = (c & 1) ? cosf(ang) : sinf(ang);
        vv[i] += pe;
    }
    f162 h0,l0,h1,l1;
    hsplit(vv[0], h0.x, l0.x); hsplit(vv[1], h0.y, l0.y);
    hsplit(vv[2], h1.x, l1.x); hsplit(vv[3], h1.y, l1.y);
    long long o = (long long)row*HH + c0;
    *(f162*)&zh[o]   = h0;  *(f162*)&zl[o]   = l0;
    *(f162*)&zh[o+2] = h1;  *(f162*)&zl[o+2] = l1;
}

// ---------------- LayerNorm (pre-summed pairs in, pairs out) ------------------
__global__ __launch_bounds__(256) void ln_kernel(
    const f16* __restrict__ Xh, const f16* __restrict__ Xl,
    const float* __restrict__ g, const float* __restrict__ b,
    f16* __restrict__ outh, f16* __restrict__ outl)
{
    __shared__ float sh[8];
    const long long row = blockIdx.x;
    const int t = threadIdx.x;
    const long long base = row*HH + t*4;
    f162 xh0 = *(const f162*)&Xh[base], xh1 = *(const f162*)&Xh[base+2];
    f162 xl0 = *(const f162*)&Xl[base], xl1 = *(const f162*)&Xl[base+2];
    float v[4];
    v[0] = __half2float(xh0.x)+__half2float(xl0.x);
    v[1] = __half2float(xh0.y)+__half2float(xl0.y);
    v[2] = __half2float(xh1.x)+__half2float(xl1.x);
    v[3] = __half2float(xh1.y)+__half2float(xl1.y);
    float s=0.f;
#pragma unroll
    for(int i=0;i<4;i++) s+=v[i];
    float mean = block_sum<8>(s, sh) * (1.0f/(float)HH);
    float sq=0.f;
#pragma unroll
    for(int i=0;i<4;i++){ float d=v[i]-mean; sq+=d*d; }
    float var = block_sum<8>(sq, sh) * (1.0f/(float)HH);
    float rstd = rsqrtf(var + 1e-5f);
    float4 gv = *(const float4*)&g[t*4];
    float4 bv = *(const float4*)&b[t*4];
    float o0 = (v[0]-mean)*rstd*gv.x + bv.x;
    float o1 = (v[1]-mean)*rstd*gv.y + bv.y;
    float o2 = (v[2]-mean)*rstd*gv.z + bv.z;
    float o3 = (v[3]-mean)*rstd*gv.w + bv.w;
    f162 h0,l0,h1,l1;
    hsplit(o0,h0.x,l0.x); hsplit(o1,h0.y,l0.y);
    hsplit(o2,h1.x,l1.x); hsplit(o3,h1.y,l1.y);
    *(f162*)&outh[base]   = h0;  *(f162*)&outl[base]   = l0;
    *(f162*)&outh[base+2] = h1;  *(f162*)&outl[base+2] = l1;
}

// ---------------- causal masked softmax -> P hi + atten_last -----------------
__global__ __launch_bounds__(128) void attn_softmax_kernel(
    const float* __restrict__ S, const int* __restrict__ lengths,
    f16* __restrict__ ph, float* __restrict__ attn_out)
{
    __shared__ float sh[4];
    const int idx = blockIdx.x;
    const int q = idx & (SS-1);
    const int b = idx >> 11;
    const float* srow = S + (long long)idx*SS;
    f16* phr = ph + (long long)idx*SS;
    const int t = threadIdx.x;
    if (q >= lengths[b]) {
#pragma unroll
        for(int i=0;i<4;i++){ int k=t+(i<<7); phr[k] = __float2half(0.f); }
        if (attn_out && t==0) attn_out[idx] = 0.f;
        return;
    }
    float v[4]; float m=-1e30f;
#pragma unroll
    for(int i=0;i<4;i++){ int k=t+(i<<7); v[i]=(k<=q)?srow[k]:-1e30f; m=fmaxf(m,v[i]); }
    m = block_max<4>(m, sh);
    float s=0.f;
#pragma unroll
    for(int i=0;i<4;i++){ v[i]=expf(v[i]-m); s+=v[i]; }
    s = block_sum<4>(s, sh);
    float r = 1.0f/s;
#pragma unroll
    for(int i=0;i<4;i++){ int k=t+(i<<7); phr[k] = __float2half(v[i]*r); }
    if (attn_out && t==0) attn_out[idx] = r;
}

// ---------------- vocab softmax ----------------------------------------------
__global__ __launch_bounds__(256) void vocab_softmax_kernel(float* __restrict__ logits)
{
    __shared__ float sh[8];
    const long long row = blockIdx.x;
    float* p = logits + row*VV;
    const int t = threadIdx.x;
    float v[32]; float m=-1e30f;
#pragma unroll
    for(int i=0;i<32;i++){ int k=t+(i<<8); v[i]=(k<VV)?p[k]:-1e30f; m=fmaxf(m,v[i]); }
    m = block_max<8>(m, sh);
    float s=0.f;
#pragma unroll
    for(int i=0;i<32;i++){ v[i]=expf(v[i]-m); s+=v[i]; }
    s = block_sum<8>(s, sh);
    float r = 1.0f/s;
#pragma unroll
    for(int i=0;i<32;i++){ int k=t+(i<<8); if(k<VV) p[k]=v[i]*r; }
}

// ---------------- host-side launch helper ------------------------------------
static void launch_tgemm(const f16*Ah,const f16*Al,const f16*Bh,
    const float*bias, const f16*Resh, const f16*Resl,
    float*C, f16*Ch, f16*Cl,
    int M,int N,int K,int lda,int ldb,int ldc,float alpha,int Nst,
    bool gelu_ep,int splita,int causal,int triK,
    int batch,int divz,long long sA1,long long sA2,long long sB1,long long sB2,
    long long sC1,long long sC2)
{
    cudaFuncSetAttribute(tgemm<0,2,0>, cudaFuncAttributeMaxDynamicSharedMemorySize, 4*24576);
    cudaFuncSetAttribute(tgemm<1,1,0>, cudaFuncAttributeMaxDynamicSharedMemorySize, 4*16384);
    cudaFuncSetAttribute(tgemm<0,1,0>, cudaFuncAttributeMaxDynamicSharedMemorySize, 4*16384);
    cudaFuncSetAttribute(tgemm<0,1,1>, cudaFuncAttributeMaxDynamicSharedMemorySize, 4*16384);
    dim3 grid(N/128, M/128, batch);
    const int smem = 4*((splita==2)?24576:16384);
    if (splita==1){
        if (Resh)
            tgemm<0,1,1><<<grid,256,smem>>>(Ah,Al,Bh,bias,Resh,Resl,C,Ch,Cl,M,N,K,lda,ldb,ldc,alpha,Nst,causal,triK,divz,sA1,sA2,sB1,sB2,sC1,sC2);
        else if (gelu_ep)
            tgemm<1,1,0><<<grid,256,smem>>>(Ah,Al,Bh,bias,nullptr,nullptr,C,Ch,Cl,M,N,K,lda,ldb,ldc,alpha,Nst,causal,triK,divz,sA1,sA2,sB1,sB2,sC1,sC2);
        else
            tgemm<0,1,0><<<grid,256,smem>>>(Ah,Al,Bh,bias,nullptr,nullptr,C,Ch,Cl,M,N,K,lda,ldb,ldc,alpha,Nst,causal,triK,divz,sA1,sA2,sB1,sB2,sC1,sC2);
    } else {
        tgemm<0,2,0><<<grid,256,smem>>>(Ah,Al,Bh,bias,nullptr,nullptr,C,Ch,Cl,M,N,K,lda,ldb,ldc,alpha,Nst,causal,triK,divz,sA1,sA2,sB1,sB2,sC1,sC2);
    }
}

#define GETSYM(var, sym) cudaGetSymbolAddress((void**)&var, sym)

extern "C" void kernel_launch(void* const* d_in, const int* in_sizes, int n_in,
                              void* d_out, int out_size)
{
    const int*   x       = (const int*)  d_in[0];
    const int*   lengths = (const int*)  d_in[1];
    const float* emb     = (const float*)d_in[2];
    const float* Wq = (const float*)d_in[3];
    const float* bq = (const float*)d_in[4];
    const float* Wk = (const float*)d_in[5];
    const float* bk = (const float*)d_in[6];
    const float* Wv = (const float*)d_in[7];
    const float* bv = (const float*)d_in[8];
    const float* W1 = (const float*)d_in[9];
    const float* b1 = (const float*)d_in[10];
    const float* W2 = (const float*)d_in[11];
    const float* b2 = (const float*)d_in[12];
    const float* g1 = (const float*)d_in[13];
    const float* be1= (const float*)d_in[14];
    const float* g2 = (const float*)d_in[15];
    const float* be2= (const float*)d_in[16];
    const float* Wfc= (const float*)d_in[17];
    const float* bfc= (const float*)d_in[18];
    float* out      = (float*)d_out;
    float* attn_out = out + (long long)NB*SS*VV;

    float *s, *bqkv;
    GETSYM(s,g_s); GETSYM(bqkv,g_bqkv);
    f16 *zh,*zl,*z1h,*z1l,*qkvh,*qkvl,*fh,*och,*ocl,*ph,*vth;
    GETSYM(zh,g_zh); GETSYM(zl,g_zl); GETSYM(z1h,g_z1h); GETSYM(z1l,g_z1l);
    GETSYM(qkvh,g_qkvh); GETSYM(qkvl,g_qkvl); GETSYM(fh,g_fh);
    GETSYM(och,g_och); GETSYM(ocl,g_ocl); GETSYM(ph,g_ph); GETSYM(vth,g_vth);
    f16 *Wqkvh,*W1h,*W2h,*Wfh,*emh;
    GETSYM(Wqkvh,g_Wqkvh); GETSYM(W1h,g_W1h); GETSYM(W2h,g_W2h);
    GETSYM(Wfh,g_Wfh); GETSYM(emh,g_emh);

    static cudaStream_t side = nullptr;
    static cudaEvent_t ev_fork = nullptr, ev_join = nullptr;
    if (!side){
        cudaStreamCreateWithFlags(&side, cudaStreamNonBlocking);
        cudaEventCreateWithFlags(&ev_fork, cudaEventDisableTiming);
        cudaEventCreateWithFlags(&ev_join, cudaEventDisableTiming);
    }

    const long long S3  = (long long)SS*H3;
    const long long SS2 = (long long)SS*SS;
    const long long SD  = (long long)SS*DHEAD;
    const int WN = LLAY*HH*HH;

    // ---- prologue: rounding on side stream || embed on main ----
    cudaEventRecord(ev_fork, 0);
    cudaStreamWaitEvent(side, ev_fork, 0);
    round_qkv_kernel<<<WN/1024,256,0,side>>>(Wq, Wqkvh, 0);
    round_qkv_kernel<<<WN/1024,256,0,side>>>(Wk, Wqkvh, 1);
    round_qkv_kernel<<<WN/1024,256,0,side>>>(Wv, Wqkvh, 2);
    bias_concat_kernel<<<LLAY*HH/256,256,0,side>>>(bq, bk, bv, bqkv);
    round_kernel<<<WN/1024,256,0,side>>>(W1, W1h, WN);
    round_kernel<<<WN/1024,256,0,side>>>(W2, W2h, WN);
    round_kernel<<<HH*HH/1024,256,0,side>>>(Wfc, Wfh, HH*HH);
    emb_round_pad_kernel<<<VPAD*HH/1024,256,0,side>>>(emb, emh);
    cudaEventRecord(ev_join, side);

    embed_kernel<<<NTOK,256>>>(x, emb, zh, zl);
    cudaStreamWaitEvent(0, ev_join, 0);

    for (int l=0;l<LLAY;l++){
        const long long wo3 = (long long)l*H3*HH;
        const long long wo  = (long long)l*HH*HH;
        const bool last = (l==LLAY-1);

        // fused QKV
        launch_tgemm(zh,zl, Wqkvh+wo3, bqkv+(long long)l*H3, nullptr,nullptr, nullptr,
                     qkvh, last?qkvl:nullptr,
                     NTOK,H3,HH, HH,HH,H3, 1.f,H3,false,1,0,0, 1,1,0,0,0,0,0,0);

        // fork: V transpose on side stream
        cudaEventRecord(ev_fork, 0);
        cudaStreamWaitEvent(side, ev_fork, 0);
        {
            dim3 gr(SS/32, DHEAD/32, NB*NHEADS);
            transpose_v_f16<<<gr,256,0,side>>>(qkvh + 2*HH, vth);
        }
        cudaEventRecord(ev_join, side);

        // scores
        launch_tgemm(qkvh, qkvl, qkvh+HH, nullptr, nullptr,nullptr, s, nullptr, nullptr,
                     SS,SS,DHEAD, H3,H3,SS, 1.0f/32.0f,SS,false, last?2:1, 1, 0,
                     NB*NHEADS, NHEADS, S3, DHEAD, S3, DHEAD,
                     (long long)NHEADS*SS2, SS2);

        attn_softmax_kernel<<<NB*NHEADS*SS,128>>>(s, lengths, ph,
                                                  last?attn_out:nullptr);

        cudaStreamWaitEvent(0, ev_join, 0);

        // O = P @ Vt^T + residual z (flat-identity layout), triK skip
        launch_tgemm(ph,ph, vth, nullptr, zh,zl, nullptr, och, ocl,
                     SS,DHEAD,SS, SS,SS,DHEAD, 1.f,DHEAD,false,1,0,1,
                     NB*NHEADS, 1, SS2, 0, SD, 0, SD, 0);

        ln_kernel<<<NTOK,256>>>(och,ocl, g1+l*HH, be1+l*HH, z1h, z1l);

        // FFN
        launch_tgemm(z1h,z1h, W1h+wo, b1+l*HH, nullptr,nullptr, nullptr, fh, nullptr,
                     NTOK,HH,HH, HH,HH,HH, 1.f,HH,true,1,0,0, 1,1,0,0,0,0,0,0);
        launch_tgemm(fh,fh, W2h+wo, b2+l*HH, z1h,z1l, nullptr, och, ocl,
                     NTOK,HH,HH, HH,HH,HH, 1.f,HH,false,1,0,0, 1,1,0,0,0,0,0,0);

        ln_kernel<<<NTOK,256>>>(och,ocl, g2+l*HH, be2+l*HH, zh, zl);
    }

    // out_fc
    launch_tgemm(zh,zl, Wfh, bfc, nullptr,nullptr, nullptr, och, ocl,
                 NTOK,HH,HH, HH,HH,HH, 1.f,HH,false,2,0,0, 1,1,0,0,0,0,0,0);
    // logits
    launch_tgemm(och,och, emh, nullptr, nullptr,nullptr, out, nullptr, nullptr,
                 NTOK,VPAD,HH, HH,HH,VV, 1.f,VV,false,1,0,0, 1,1,0,0,0,0,0,0);
    vocab_softmax_kernel<<<NTOK,256>>>(out);
}

// round 15
// speedup vs baseline: 1.0408x; 1.0408x over previous
#include <cuda_runtime.h>
#include <cuda_fp16.h>
#include <math.h>
#include <stdint.h>

#define NB     16
#define SS     512
#define HH     1024
#define H3     (3*HH)
#define VV     8000
#define VPAD   8064
#define LLAY   8
#define NHEADS 4
#define DHEAD  256
#define NTOK   (NB*SS)

typedef __half  f16;
typedef __half2 f162;

// ---------------- scratch (__device__ globals) --------------------------------
__device__ f16 g_sh  [NB*NHEADS*SS*SS];           // attention scores f16
__device__ f16 g_zh  [NTOK*HH],  g_zl [NTOK*HH];  // residual stream pairs
__device__ f16 g_z1h [NTOK*HH],  g_z1l[NTOK*HH];
__device__ f16 g_qkvh[NTOK*H3],  g_qkvl[NTOK*H3]; // fused QKV out (lo: layer7 only)
__device__ f16 g_fh  [NTOK*HH];                   // FFN1 out (hi only)
__device__ f16 g_och [NTOK*HH],  g_ocl[NTOK*HH];  // attn-out / FFN2-out / fc-out pairs
__device__ f16 g_ph  [NB*NHEADS*SS*SS];           // P hi only
__device__ f16 g_vth [NTOK*HH];                   // V^T [bh][dh][S]
__device__ f16 g_Wqkvh[LLAY*H3*HH];
__device__ f16 g_W1h[LLAY*HH*HH];
__device__ f16 g_W2h[LLAY*HH*HH];
__device__ f16 g_Wfh[HH*HH];
__device__ f16 g_emh[VPAD*HH];
__device__ float g_bqkv[LLAY*H3];

// ---------------- helpers -----------------------------------------------------
__device__ __forceinline__ void hsplit(float x, f16& h, f16& l){
    h = __float2half(x);
    l = __float2half(x - __half2float(h));
}
__device__ __forceinline__ void mma_f16(float* c, const uint32_t* a, const uint32_t* b){
    asm volatile("mma.sync.aligned.m16n8k16.row.col.f32.f16.f16.f32 "
        "{%0,%1,%2,%3}, {%4,%5,%6,%7}, {%8,%9}, {%0,%1,%2,%3};"
        : "+f"(c[0]),"+f"(c[1]),"+f"(c[2]),"+f"(c[3])
        : "r"(a[0]),"r"(a[1]),"r"(a[2]),"r"(a[3]), "r"(b[0]),"r"(b[1]));
}
__device__ __forceinline__ void ldsm4(uint32_t* r, uint32_t addr){
    asm volatile("ldmatrix.sync.aligned.m8n8.x4.shared.b16 {%0,%1,%2,%3}, [%4];"
        : "=r"(r[0]),"=r"(r[1]),"=r"(r[2]),"=r"(r[3]) : "r"(addr));
}
__device__ __forceinline__ uint32_t s2u(const void* p){
    uint32_t a;
    asm("{ .reg .u64 t; cvta.to.shared.u64 t, %1; cvt.u32.u64 %0, t; }" : "=r"(a) : "l"(p));
    return a;
}
__device__ __forceinline__ void cp16(uint32_t dst, const void* src){
    asm volatile("cp.async.cg.shared.global [%0], [%1], 16;" :: "r"(dst), "l"(src));
}

// ================= fp16 NT GEMM: ldmatrix, cp.async 4-stage ===================
// SPLITA=2: A = Ah+Al; SPLITA=1: A hi only. Tile 128x128x32, 256 thr.
// causal!=0: skip tiles n0 > m0+127.  triK!=0: effective K = m0+128 (P@V skip).
template<int EPI, int SPLITA>
__global__ void __launch_bounds__(256,2) tgemm(
    const f16* __restrict__ Ah, const f16* __restrict__ Al,
    const f16* __restrict__ Bh,
    const float* __restrict__ bias,
    float* __restrict__ C, f16* __restrict__ Ch, f16* __restrict__ Cl,
    int M, int N, int K, int lda, int ldb, int ldc, float alpha, int Nst,
    int causal, int triK,
    int divz, long long sA1, long long sA2, long long sB1, long long sB2,
    long long sC1, long long sC2)
{
    constexpr uint32_t STGB = (SPLITA==2) ? 24576u : 16384u;
    constexpr uint32_t BOFF = (SPLITA==2) ? 16384u : 8192u;
    extern __shared__ char smem[];
    const int m0 = blockIdx.y*128, n0 = blockIdx.x*128;
    if (causal && n0 > m0 + 127) return;

    const int z = blockIdx.z;
    const long long offA = (long long)(z/divz)*sA1 + (long long)(z%divz)*sA2;
    const long long offB = (long long)(z/divz)*sB1 + (long long)(z%divz)*sB2;
    const long long offC = (long long)(z/divz)*sC1 + (long long)(z%divz)*sC2;
    Ah += offA; Al += offA; Bh += offB;

    const int tid = threadIdx.x;
    const int wid = tid>>5, lane = tid&31;
    const int g = lane>>2, t = lane&3;
    const int m0w = (wid&1)*64, n0w = (wid>>1)*32;

    const int a_ro = ((lane>>3)&1)*8 + (lane&7);
    const int a_kh = lane>>4;
    const int a_sw = (a_ro>>1)&3;
    const int b_ro = (lane>>4)*8 + (lane&7);
    const int b_kh = (lane>>3)&1;
    const int b_sw = (b_ro>>1)&3;

    const uint32_t sb = s2u(smem);
    const int srow = tid>>2;
    const int sch  = tid&3;
    const uint32_t soff0 = (uint32_t)(srow*64 + ((sch  ^ ((srow>>1)&3))<<4));
    const int srow1 = (tid+256)>>2;
    const uint32_t soff1 = (uint32_t)(srow1*64 + ((sch ^ ((srow1>>1)&3))<<4));

    float acc[4][4][4];
#pragma unroll
    for (int i=0;i<4;i++)
#pragma unroll
        for (int j=0;j<4;j++)
#pragma unroll
            for (int r=0;r<4;r++) acc[i][j][r]=0.f;

    const int Keff = triK ? (m0 + 128) : K;
    const int nch = Keff >> 5;

    auto stage_chunk = [&](int c, int st){
        const uint32_t base = sb + (uint32_t)st*STGB;
        const int kc = c*32;
        {
            const long long ga = (long long)(m0+srow)*lda + kc + sch*8;
            const long long gb = (long long)(n0+srow)*ldb + kc + sch*8;
            cp16(base +        soff0, Ah + ga);
            if (SPLITA==2) cp16(base + 8192 + soff0, Al + ga);
            cp16(base + BOFF + soff0, Bh + gb);
        }
        {
            const long long ga = (long long)(m0+srow1)*lda + kc + sch*8;
            const long long gb = (long long)(n0+srow1)*ldb + kc + sch*8;
            cp16(base +        soff1, Ah + ga);
            if (SPLITA==2) cp16(base + 8192 + soff1, Al + ga);
            cp16(base + BOFF + soff1, Bh + gb);
        }
        asm volatile("cp.async.commit_group;");
    };

    stage_chunk(0,0);
    stage_chunk(1,1);
    stage_chunk(2,2);

    for (int c=0; c<nch; c++){
        const int st = c & 3;
        if      (c+2 < nch) asm volatile("cp.async.wait_group 2;");
        else if (c+1 < nch) asm volatile("cp.async.wait_group 1;");
        else                asm volatile("cp.async.wait_group 0;");
        __syncthreads();
        if (c+3 < nch) stage_chunk(c+3, (c+3)&3);

        const uint32_t base = sb + (uint32_t)st*STGB;
#pragma unroll
        for (int ks=0; ks<2; ks++){
            uint32_t bh[4][2];
#pragma unroll
            for (int jp=0; jp<2; jp++){
                uint32_t r4[4];
                const uint32_t addrB = base + BOFF
                    + (uint32_t)(n0w + jp*16 + b_ro)*64u
                    + (uint32_t)(((ks*2 + b_kh) ^ b_sw)<<4);
                ldsm4(r4, addrB);
                bh[2*jp  ][0] = r4[0]; bh[2*jp  ][1] = r4[1];
                bh[2*jp+1][0] = r4[2]; bh[2*jp+1][1] = r4[3];
            }
#pragma unroll
            for (int i=0;i<4;i++){
                const uint32_t addrA = base
                    + (uint32_t)(m0w + i*16 + a_ro)*64u
                    + (uint32_t)(((ks*2 + a_kh) ^ a_sw)<<4);
                uint32_t ah[4];
                ldsm4(ah, addrA);
                uint32_t al[4];
                if (SPLITA==2) ldsm4(al, addrA + 8192u);
#pragma unroll
                for (int j=0;j<4;j++){
                    mma_f16(acc[i][j], ah, bh[j]);
                    if (SPLITA==2) mma_f16(acc[i][j], al, bh[j]);
                }
            }
        }
    }

    // ---- epilogue ----
#pragma unroll
    for (int i=0;i<4;i++){
        const long long r0 = m0 + m0w + i*16 + g;
        const long long r1 = r0 + 8;
#pragma unroll
        for (int j=0;j<4;j++){
            const int col = n0 + n0w + j*8 + 2*t;
            if (col < Nst){
                float b0=0.f, b1=0.f;
                if (bias){ b0 = bias[col]; b1 = bias[col+1]; }
                float c0 = acc[i][j][0]*alpha + b0;
                float c1 = acc[i][j][1]*alpha + b1;
                float c2 = acc[i][j][2]*alpha + b0;
                float c3 = acc[i][j][3]*alpha + b1;
                if (EPI==1){
                    c0 = 0.5f*c0*(1.0f+erff(c0*0.70710678118654752440f));
                    c1 = 0.5f*c1*(1.0f+erff(c1*0.70710678118654752440f));
                    c2 = 0.5f*c2*(1.0f+erff(c2*0.70710678118654752440f));
                    c3 = 0.5f*c3*(1.0f+erff(c3*0.70710678118654752440f));
                }
                if (C){
                    *(float2*)&C[(offC + r0*ldc) + col] = make_float2(c0,c1);
                    *(float2*)&C[(offC + r1*ldc) + col] = make_float2(c2,c3);
                }
                if (Ch){
                    if (Cl){
                        f162 h0,l0,h1,l1;
                        hsplit(c0,h0.x,l0.x); hsplit(c1,h0.y,l0.y);
                        hsplit(c2,h1.x,l1.x); hsplit(c3,h1.y,l1.y);
                        *(f162*)&Ch[(offC + r0*ldc) + col] = h0;
                        *(f162*)&Cl[(offC + r0*ldc) + col] = l0;
                        *(f162*)&Ch[(offC + r1*ldc) + col] = h1;
                        *(f162*)&Cl[(offC + r1*ldc) + col] = l1;
                    } else {
                        *(f162*)&Ch[(offC + r0*ldc) + col] = __floats2half2_rn(c0,c1);
                        *(f162*)&Ch[(offC + r1*ldc) + col] = __floats2half2_rn(c2,c3);
                    }
                }
            }
        }
    }
}

// ---------------- weight rounding -------------------------------------------
__global__ __launch_bounds__(256) void round_kernel(
    const float* __restrict__ in, f16* __restrict__ h, int n)
{
    int i = (blockIdx.x*256 + threadIdx.x)*4;
    if (i < n){
        float4 v = *(const float4*)&in[i];
        *(f162*)&h[i]   = __floats2half2_rn(v.x, v.y);
        *(f162*)&h[i+2] = __floats2half2_rn(v.z, v.w);
    }
}
__global__ __launch_bounds__(256) void round_qkv_kernel(
    const float* __restrict__ in, f16* __restrict__ out, int part)
{
    int i = (blockIdx.x*256 + threadIdx.x)*4;       // over L*H*H
    int l = i / (HH*HH), r = i % (HH*HH);
    long long o = (long long)l*H3*HH + (long long)part*HH*HH + r;
    float4 v = *(const float4*)&in[i];
    *(f162*)&out[o]   = __floats2half2_rn(v.x, v.y);
    *(f162*)&out[o+2] = __floats2half2_rn(v.z, v.w);
}
__global__ __launch_bounds__(256) void bias_concat_kernel(
    const float* __restrict__ bq, const float* __restrict__ bk,
    const float* __restrict__ bv, float* __restrict__ o)
{
    int i = blockIdx.x*256 + threadIdx.x;           // over L*HH
    int l = i/HH, c = i%HH;
    o[(long long)l*H3 + c]        = bq[i];
    o[(long long)l*H3 + HH + c]   = bk[i];
    o[(long long)l*H3 + 2*HH + c] = bv[i];
}
__global__ __launch_bounds__(256) void emb_round_pad_kernel(
    const float* __restrict__ emb, f16* __restrict__ h)
{
    int i = (blockIdx.x*256 + threadIdx.x)*4;
    int row = i >> 10;
    float4 v = make_float4(0.f,0.f,0.f,0.f);
    if (row < VV) v = *(const float4*)&emb[(long long)row*HH + (i & 1023)];
    *(f162*)&h[i]   = __floats2half2_rn(v.x, v.y);
    *(f162*)&h[i+2] = __floats2half2_rn(v.z, v.w);
}

// ---------------- V transpose from qkv slice ---------------------------------
__global__ __launch_bounds__(256) void transpose_v_f16(
    const f16* __restrict__ V, f16* __restrict__ Vth)   // V = qkvh + 2*HH
{
    __shared__ float tbuf[32][33];
    const int bh = blockIdx.z, b = bh >> 2, h = bh & 3;
    const int s0 = blockIdx.x*32, d0 = blockIdx.y*32;
    const int tx = threadIdx.x & 31, ty = threadIdx.x >> 5;
#pragma unroll
    for (int i=0;i<4;i++){
        int r = ty + i*8;
        tbuf[r][tx] = __half2float(V[(long long)(b*SS + s0 + r)*H3 + h*DHEAD + d0 + tx]);
    }
    __syncthreads();
#pragma unroll
    for (int i=0;i<4;i++){
        int r = ty + i*8;
        Vth[(long long)(bh*DHEAD + d0 + r)*SS + s0 + tx] = __float2half(tbuf[tx][r]);
    }
}

// ---------------- reductions -------------------------------------------------
__device__ __forceinline__ float warp_sum(float v){
#pragma unroll
    for(int o=16;o;o>>=1) v += __shfl_xor_sync(0xffffffffu,v,o);
    return v;
}
__device__ __forceinline__ float warp_max(float v){
#pragma unroll
    for(int o=16;o;o>>=1) v = fmaxf(v,__shfl_xor_sync(0xffffffffu,v,o));
    return v;
}
template<int NW>
__device__ __forceinline__ float block_sum(float v, float* sh){
    v = warp_sum(v);
    if((threadIdx.x&31)==0) sh[threadIdx.x>>5]=v;
    __syncthreads();
    float t=0.f;
#pragma unroll
    for(int i=0;i<NW;i++) t+=sh[i];
    __syncthreads();
    return t;
}
template<int NW>
__device__ __forceinline__ float block_max(float v, float* sh){
    v = warp_max(v);
    if((threadIdx.x&31)==0) sh[threadIdx.x>>5]=v;
    __syncthreads();
    float t=-1e30f;
#pragma unroll
    for(int i=0;i<NW;i++) t=fmaxf(t,sh[i]);
    __syncthreads();
    return t;
}

// ---------------- embedding + PE -> f16 pairs --------------------------------
__global__ __launch_bounds__(256) void embed_kernel(
    const int* __restrict__ x, const float* __restrict__ emb,
    f16* __restrict__ zh, f16* __restrict__ zl)
{
    const int row = blockIdx.x;
    const int s = row & (SS-1);
    const int tok = x[row];
    const int c0 = threadIdx.x*4;
    float4 ev = *(const float4*)&emb[(long long)tok*HH + c0];
    float vv[4] = {ev.x, ev.y, ev.z, ev.w};
#pragma unroll
    for(int i=0;i<4;i++){
        int c = c0 + i;
        int half = c >> 1;
        float dv = expf(-(float)(2*half) * (9.210340371976184f/(float)HH));
        float ang = (float)s * dv;
        float pe = (c & 1) ? cosf(ang) : sinf(ang);
        vv[i] += pe;
    }
    f162 h0,l0,h1,l1;
    hsplit(vv[0], h0.x, l0.x); hsplit(vv[1], h0.y, l0.y);
    hsplit(vv[2], h1.x, l1.x); hsplit(vv[3], h1.y, l1.y);
    long long o = (long long)row*HH + c0;
    *(f162*)&zh[o]   = h0;  *(f162*)&zl[o]   = l0;
    *(f162*)&zh[o+2] = h1;  *(f162*)&zl[o+2] = l1;
}

// ---------------- fused residual-add + LayerNorm (pairs) ---------------------
__global__ __launch_bounds__(256) void add_ln_kernel(
    const f16* __restrict__ Xh, const f16* __restrict__ Xl,
    const f16* __restrict__ Rh, const f16* __restrict__ Rl,
    const float* __restrict__ g, const float* __restrict__ b,
    f16* __restrict__ outh, f16* __restrict__ outl)
{
    __shared__ float sh[8];
    const long long row = blockIdx.x;
    const int t = threadIdx.x;
    const long long base = row*HH + t*4;
    f162 xh0 = *(const f162*)&Xh[base], xh1 = *(const f162*)&Xh[base+2];
    f162 xl0 = *(const f162*)&Xl[base], xl1 = *(const f162*)&Xl[base+2];
    f162 rh0 = *(const f162*)&Rh[base], rh1 = *(const f162*)&Rh[base+2];
    f162 rl0 = *(const f162*)&Rl[base], rl1 = *(const f162*)&Rl[base+2];
    float v[4];
    v[0] = __half2float(xh0.x)+__half2float(xl0.x)+__half2float(rh0.x)+__half2float(rl0.x);
    v[1] = __half2float(xh0.y)+__half2float(xl0.y)+__half2float(rh0.y)+__half2float(rl0.y);
    v[2] = __half2float(xh1.x)+__half2float(xl1.x)+__half2float(rh1.x)+__half2float(rl1.x);
    v[3] = __half2float(xh1.y)+__half2float(xl1.y)+__half2float(rh1.y)+__half2float(rl1.y);
    float s=0.f;
#pragma unroll
    for(int i=0;i<4;i++) s+=v[i];
    float mean = block_sum<8>(s, sh) * (1.0f/(float)HH);
    float sq=0.f;
#pragma unroll
    for(int i=0;i<4;i++){ float d=v[i]-mean; sq+=d*d; }
    float var = block_sum<8>(sq, sh) * (1.0f/(float)HH);
    float rstd = rsqrtf(var + 1e-5f);
    float4 gv = *(const float4*)&g[t*4];
    float4 bv = *(const float4*)&b[t*4];
    float o0 = (v[0]-mean)*rstd*gv.x + bv.x;
    float o1 = (v[1]-mean)*rstd*gv.y + bv.y;
    float o2 = (v[2]-mean)*rstd*gv.z + bv.z;
    float o3 = (v[3]-mean)*rstd*gv.w + bv.w;
    f162 h0,l0,h1,l1;
    hsplit(o0,h0.x,l0.x); hsplit(o1,h0.y,l0.y);
    hsplit(o2,h1.x,l1.x); hsplit(o3,h1.y,l1.y);
    *(f162*)&outh[base]   = h0;  *(f162*)&outl[base]   = l0;
    *(f162*)&outh[base+2] = h1;  *(f162*)&outl[base+2] = l1;
}

// ---------------- causal masked softmax (f16 scores) -> P hi + atten_last ----
__global__ __launch_bounds__(128) void attn_softmax_kernel(
    const f16* __restrict__ S, const int* __restrict__ lengths,
    f16* __restrict__ ph, float* __restrict__ attn_out)
{
    __shared__ float sh[4];
    const int idx = blockIdx.x;
    const int q = idx & (SS-1);
    const int b = idx >> 11;
    const f16* srow = S + (long long)idx*SS;
    f16* phr = ph + (long long)idx*SS;
    const int t = threadIdx.x;
    if (q >= lengths[b]) {
#pragma unroll
        for(int i=0;i<4;i++){ int k=t+(i<<7); phr[k] = __float2half(0.f); }
        if (attn_out && t==0) attn_out[idx] = 0.f;
        return;
    }
    float v[4]; float m=-1e30f;
#pragma unroll
    for(int i=0;i<4;i++){
        int k=t+(i<<7);
        v[i] = (k<=q) ? __half2float(srow[k]) : -1e30f;
        m = fmaxf(m,v[i]);
    }
    m = block_max<4>(m, sh);
    float s=0.f;
#pragma unroll
    for(int i=0;i<4;i++){ v[i]=expf(v[i]-m); s+=v[i]; }
    s = block_sum<4>(s, sh);
    float r = 1.0f/s;
#pragma unroll
    for(int i=0;i<4;i++){ int k=t+(i<<7); phr[k] = __float2half(v[i]*r); }
    if (attn_out && t==0) attn_out[idx] = r;
}

// ---------------- vocab softmax ----------------------------------------------
__global__ __launch_bounds__(256) void vocab_softmax_kernel(float* __restrict__ logits)
{
    __shared__ float sh[8];
    const long long row = blockIdx.x;
    float* p = logits + row*VV;
    const int t = threadIdx.x;
    float v[32]; float m=-1e30f;
#pragma unroll
    for(int i=0;i<32;i++){ int k=t+(i<<8); v[i]=(k<VV)?p[k]:-1e30f; m=fmaxf(m,v[i]); }
    m = block_max<8>(m, sh);
    float s=0.f;
#pragma unroll
    for(int i=0;i<32;i++){ v[i]=expf(v[i]-m); s+=v[i]; }
    s = block_sum<8>(s, sh);
    float r = 1.0f/s;
#pragma unroll
    for(int i=0;i<32;i++){ int k=t+(i<<8); if(k<VV) p[k]=v[i]*r; }
}

// ---------------- host-side launch helper ------------------------------------
static void launch_tgemm(const f16*Ah,const f16*Al,const f16*Bh,
    const float*bias, float*C, f16*Ch, f16*Cl,
    int M,int N,int K,int lda,int ldb,int ldc,float alpha,int Nst,
    bool gelu_ep,int splita,int causal,int triK,
    int batch,int divz,long long sA1,long long sA2,long long sB1,long long sB2,
    long long sC1,long long sC2)
{
    cudaFuncSetAttribute(tgemm<0,2>, cudaFuncAttributeMaxDynamicSharedMemorySize, 4*24576);
    cudaFuncSetAttribute(tgemm<1,1>, cudaFuncAttributeMaxDynamicSharedMemorySize, 4*16384);
    cudaFuncSetAttribute(tgemm<0,1>, cudaFuncAttributeMaxDynamicSharedMemorySize, 4*16384);
    dim3 grid(N/128, M/128, batch);
    const int smem = 4*((splita==2)?24576:16384);
    if (splita==1){
        if (gelu_ep)
            tgemm<1,1><<<grid,256,smem>>>(Ah,Al,Bh,bias,C,Ch,Cl,M,N,K,lda,ldb,ldc,alpha,Nst,causal,triK,divz,sA1,sA2,sB1,sB2,sC1,sC2);
        else
            tgemm<0,1><<<grid,256,smem>>>(Ah,Al,Bh,bias,C,Ch,Cl,M,N,K,lda,ldb,ldc,alpha,Nst,causal,triK,divz,sA1,sA2,sB1,sB2,sC1,sC2);
    } else {
        tgemm<0,2><<<grid,256,smem>>>(Ah,Al,Bh,bias,C,Ch,Cl,M,N,K,lda,ldb,ldc,alpha,Nst,causal,triK,divz,sA1,sA2,sB1,sB2,sC1,sC2);
    }
}

#define GETSYM(var, sym) cudaGetSymbolAddress((void**)&var, sym)

extern "C" void kernel_launch(void* const* d_in, const int* in_sizes, int n_in,
                              void* d_out, int out_size)
{
    const int*   x       = (const int*)  d_in[0];
    const int*   lengths = (const int*)  d_in[1];
    const float* emb     = (const float*)d_in[2];
    const float* Wq = (const float*)d_in[3];
    const float* bq = (const float*)d_in[4];
    const float* Wk = (const float*)d_in[5];
    const float* bk = (const float*)d_in[6];
    const float* Wv = (const float*)d_in[7];
    const float* bv = (const float*)d_in[8];
    const float* W1 = (const float*)d_in[9];
    const float* b1 = (const float*)d_in[10];
    const float* W2 = (const float*)d_in[11];
    const float* b2 = (const float*)d_in[12];
    const float* g1 = (const float*)d_in[13];
    const float* be1= (const float*)d_in[14];
    const float* g2 = (const float*)d_in[15];
    const float* be2= (const float*)d_in[16];
    const float* Wfc= (const float*)d_in[17];
    const float* bfc= (const float*)d_in[18];
    float* out      = (float*)d_out;
    float* attn_out = out + (long long)NB*SS*VV;

    float *bqkv;
    GETSYM(bqkv,g_bqkv);
    f16 *sh16,*zh,*zl,*z1h,*z1l,*qkvh,*qkvl,*fh,*och,*ocl,*ph,*vth;
    GETSYM(sh16,g_sh);
    GETSYM(zh,g_zh); GETSYM(zl,g_zl); GETSYM(z1h,g_z1h); GETSYM(z1l,g_z1l);
    GETSYM(qkvh,g_qkvh); GETSYM(qkvl,g_qkvl); GETSYM(fh,g_fh);
    GETSYM(och,g_och); GETSYM(ocl,g_ocl); GETSYM(ph,g_ph); GETSYM(vth,g_vth);
    f16 *Wqkvh,*W1h,*W2h,*Wfh,*emh;
    GETSYM(Wqkvh,g_Wqkvh); GETSYM(W1h,g_W1h); GETSYM(W2h,g_W2h);
    GETSYM(Wfh,g_Wfh); GETSYM(emh,g_emh);

    const long long S3  = (long long)SS*H3;
    const long long SS2 = (long long)SS*SS;
    const long long SD  = (long long)SS*DHEAD;
    const int WN = LLAY*HH*HH;

    // ---- pack + round weights ----
    round_qkv_kernel<<<WN/1024,256>>>(Wq, Wqkvh, 0);
    round_qkv_kernel<<<WN/1024,256>>>(Wk, Wqkvh, 1);
    round_qkv_kernel<<<WN/1024,256>>>(Wv, Wqkvh, 2);
    bias_concat_kernel<<<LLAY*HH/256,256>>>(bq, bk, bv, bqkv);
    round_kernel<<<WN/1024,256>>>(W1, W1h, WN);
    round_kernel<<<WN/1024,256>>>(W2, W2h, WN);
    round_kernel<<<HH*HH/1024,256>>>(Wfc, Wfh, HH*HH);
    emb_round_pad_kernel<<<VPAD*HH/1024,256>>>(emb, emh);

    embed_kernel<<<NTOK,256>>>(x, emb, zh, zl);

    for (int l=0;l<LLAY;l++){
        const long long wo3 = (long long)l*H3*HH;
        const long long wo  = (long long)l*HH*HH;
        const bool last = (l==LLAY-1);

        // fused QKV: [8192,3072] = z @ Wqkv^T + bqkv; pairs only for last layer
        launch_tgemm(zh,zl, Wqkvh+wo3, bqkv+(long long)l*H3, nullptr,
                     qkvh, last?qkvl:nullptr,
                     NTOK,H3,HH, HH,HH,H3, 1.f,H3,false,1,0,0, 1,1,0,0,0,0,0,0);

        // V -> Vt [bh][dh][S] from qkv slice
        {
            dim3 gr(SS/32, DHEAD/32, NB*NHEADS);
            transpose_v_f16<<<gr,256>>>(qkvh + 2*HH, vth);
        }

        // scores: Q@K^T/32 -> f16, causal skip; split Q only on last layer
        launch_tgemm(qkvh, qkvl, qkvh+HH, nullptr, nullptr, sh16, nullptr,
                     SS,SS,DHEAD, H3,H3,SS, 1.0f/32.0f,SS,false, last?2:1, 1, 0,
                     NB*NHEADS, NHEADS, S3, DHEAD, S3, DHEAD,
                     (long long)NHEADS*SS2, SS2);

        attn_softmax_kernel<<<NB*NHEADS*SS,128>>>(sh16, lengths, ph,
                                                  last?attn_out:nullptr);

        // O = P @ Vt^T, triangular K skip, out pairs
        launch_tgemm(ph,ph, vth, nullptr, nullptr, och, ocl,
                     SS,DHEAD,SS, SS,SS,DHEAD, 1.f,DHEAD,false,1,0,1,
                     NB*NHEADS, 1, SS2, 0, SD, 0, SD, 0);

        add_ln_kernel<<<NTOK,256>>>(zh,zl, och,ocl, g1+l*HH, be1+l*HH, z1h, z1l);

        // FFN (A hi-only; FFN1 out hi-only)
        launch_tgemm(z1h,z1h, W1h+wo, b1+l*HH, nullptr, fh, nullptr,
                     NTOK,HH,HH, HH,HH,HH, 1.f,HH,true,1,0,0, 1,1,0,0,0,0,0,0);
        launch_tgemm(fh,fh, W2h+wo, b2+l*HH, nullptr, och, ocl,
                     NTOK,HH,HH, HH,HH,HH, 1.f,HH,false,1,0,0, 1,1,0,0,0,0,0,0);

        add_ln_kernel<<<NTOK,256>>>(z1h,z1l, och,ocl, g2+l*HH, be2+l*HH, zh, zl);
    }

    // out_fc = z @ Wfc^T + bfc (A split) -> pairs
    launch_tgemm(zh,zl, Wfh, bfc, nullptr, och, ocl,
                 NTOK,HH,HH, HH,HH,HH, 1.f,HH,false,2,0,0, 1,1,0,0,0,0,0,0);
    // logits = out_fc @ emb^T, A hi-only
    launch_tgemm(och,och, emh, nullptr, out, nullptr, nullptr,
                 NTOK,VPAD,HH, HH,HH,VV, 1.f,VV,false,1,0,0, 1,1,0,0,0,0,0,0);
    vocab_softmax_kernel<<<NTOK,256>>>(out);
}

// round 16
// speedup vs baseline: 1.0436x; 1.0026x over previous
#include <cuda_runtime.h>
#include <cuda_fp16.h>
#include <math.h>
#include <stdint.h>

#define NB     16
#define SS     512
#define HH     1024
#define H3     (3*HH)
#define VV     8000
#define VPAD   8064
#define LLAY   8
#define NHEADS 4
#define DHEAD  256
#define NTOK   (NB*SS)

typedef __half  f16;
typedef __half2 f162;

// ---------------- scratch (__device__ globals) --------------------------------
__device__ f16 g_sh  [NB*NHEADS*SS*SS];           // attention scores f16
__device__ f16 g_zh  [NTOK*HH],  g_zl [NTOK*HH];  // residual stream pairs
__device__ f16 g_z1h [NTOK*HH],  g_z1l[NTOK*HH];
__device__ f16 g_qkvh[NTOK*H3],  g_qkvl[NTOK*H3]; // fused QKV out (lo: layer7 only)
__device__ f16 g_fh  [NTOK*HH];                   // FFN1 out (hi only)
__device__ f16 g_och [NTOK*HH],  g_ocl[NTOK*HH];  // attn-out / FFN2-out / fc-out pairs
__device__ f16 g_ph  [NB*NHEADS*SS*SS];           // P hi only
__device__ f16 g_vth [NTOK*HH];                   // V^T [bh][dh][S]
__device__ f16 g_Wqkvh[LLAY*H3*HH];
__device__ f16 g_W1h[LLAY*HH*HH];
__device__ f16 g_W2h[LLAY*HH*HH];
__device__ f16 g_Wfh[HH*HH];
__device__ f16 g_emh[VPAD*HH];
__device__ float g_bqkv[LLAY*H3];

// ---------------- helpers -----------------------------------------------------
__device__ __forceinline__ void hsplit(float x, f16& h, f16& l){
    h = __float2half(x);
    l = __float2half(x - __half2float(h));
}
__device__ __forceinline__ void mma_f16(float* c, const uint32_t* a, const uint32_t* b){
    asm volatile("mma.sync.aligned.m16n8k16.row.col.f32.f16.f16.f32 "
        "{%0,%1,%2,%3}, {%4,%5,%6,%7}, {%8,%9}, {%0,%1,%2,%3};"
        : "+f"(c[0]),"+f"(c[1]),"+f"(c[2]),"+f"(c[3])
        : "r"(a[0]),"r"(a[1]),"r"(a[2]),"r"(a[3]), "r"(b[0]),"r"(b[1]));
}
__device__ __forceinline__ void ldsm4(uint32_t* r, uint32_t addr){
    asm volatile("ldmatrix.sync.aligned.m8n8.x4.shared.b16 {%0,%1,%2,%3}, [%4];"
        : "=r"(r[0]),"=r"(r[1]),"=r"(r[2]),"=r"(r[3]) : "r"(addr));
}
__device__ __forceinline__ uint32_t s2u(const void* p){
    uint32_t a;
    asm("{ .reg .u64 t; cvta.to.shared.u64 t, %1; cvt.u32.u64 %0, t; }" : "=r"(a) : "l"(p));
    return a;
}
__device__ __forceinline__ void cp16(uint32_t dst, const void* src){
    asm volatile("cp.async.cg.shared.global [%0], [%1], 16;" :: "r"(dst), "l"(src));
}

// ================= fp16 NT GEMM: ldmatrix, cp.async 4-stage ===================
// SPLITA=2: A = Ah+Al; SPLITA=1: A hi only. Tile 128x128x32, 256 thr.
// causal!=0: compact lower-triangle grid — blockIdx.x encodes the (m,n) tile
//            pair of the 4x4 lower triangle (10 pairs).
// triK!=0:  effective K = m0+128 (P@V upper-triangle skip); tiles remapped
//            heavy-first (m0 descending in blockIdx.y) for wave packing.
template<int EPI, int SPLITA>
__global__ void __launch_bounds__(256,2) tgemm(
    const f16* __restrict__ Ah, const f16* __restrict__ Al,
    const f16* __restrict__ Bh,
    const float* __restrict__ bias,
    float* __restrict__ C, f16* __restrict__ Ch, f16* __restrict__ Cl,
    int M, int N, int K, int lda, int ldb, int ldc, float alpha, int Nst,
    int causal, int triK,
    int divz, long long sA1, long long sA2, long long sB1, long long sB2,
    long long sC1, long long sC2)
{
    constexpr uint32_t STGB = (SPLITA==2) ? 24576u : 16384u;
    constexpr uint32_t BOFF = (SPLITA==2) ? 16384u : 8192u;
    extern __shared__ char smem[];

    int m0, n0;
    if (causal){
        // decode pair p -> (m,n), n<=m, of the 4x4 lower triangle
        const int p = blockIdx.x;
        const int mi = (p>=6) ? 3 : (p>=3) ? 2 : (p>=1) ? 1 : 0;
        const int ni = p - ((mi*(mi+1))>>1);
        m0 = mi*128; n0 = ni*128;
    } else if (triK){
        m0 = (gridDim.y - 1 - blockIdx.y)*128;   // heavy tiles first
        n0 = blockIdx.x*128;
    } else {
        m0 = blockIdx.y*128; n0 = blockIdx.x*128;
    }

    const int z = blockIdx.z;
    const long long offA = (long long)(z/divz)*sA1 + (long long)(z%divz)*sA2;
    const long long offB = (long long)(z/divz)*sB1 + (long long)(z%divz)*sB2;
    const long long offC = (long long)(z/divz)*sC1 + (long long)(z%divz)*sC2;
    Ah += offA; Al += offA; Bh += offB;

    const int tid = threadIdx.x;
    const int wid = tid>>5, lane = tid&31;
    const int g = lane>>2, t = lane&3;
    const int m0w = (wid&1)*64, n0w = (wid>>1)*32;

    const int a_ro = ((lane>>3)&1)*8 + (lane&7);
    const int a_kh = lane>>4;
    const int a_sw = (a_ro>>1)&3;
    const int b_ro = (lane>>4)*8 + (lane&7);
    const int b_kh = (lane>>3)&1;
    const int b_sw = (b_ro>>1)&3;

    const uint32_t sb = s2u(smem);
    const int srow = tid>>2;
    const int sch  = tid&3;
    const uint32_t soff0 = (uint32_t)(srow*64 + ((sch  ^ ((srow>>1)&3))<<4));
    const int srow1 = (tid+256)>>2;
    const uint32_t soff1 = (uint32_t)(srow1*64 + ((sch ^ ((srow1>>1)&3))<<4));

    float acc[4][4][4];
#pragma unroll
    for (int i=0;i<4;i++)
#pragma unroll
        for (int j=0;j<4;j++)
#pragma unroll
            for (int r=0;r<4;r++) acc[i][j][r]=0.f;

    const int Keff = triK ? (m0 + 128) : K;
    const int nch = Keff >> 5;

    auto stage_chunk = [&](int c, int st){
        const uint32_t base = sb + (uint32_t)st*STGB;
        const int kc = c*32;
        {
            const long long ga = (long long)(m0+srow)*lda + kc + sch*8;
            const long long gb = (long long)(n0+srow)*ldb + kc + sch*8;
            cp16(base +        soff0, Ah + ga);
            if (SPLITA==2) cp16(base + 8192 + soff0, Al + ga);
            cp16(base + BOFF + soff0, Bh + gb);
        }
        {
            const long long ga = (long long)(m0+srow1)*lda + kc + sch*8;
            const long long gb = (long long)(n0+srow1)*ldb + kc + sch*8;
            cp16(base +        soff1, Ah + ga);
            if (SPLITA==2) cp16(base + 8192 + soff1, Al + ga);
            cp16(base + BOFF + soff1, Bh + gb);
        }
        asm volatile("cp.async.commit_group;");
    };

    stage_chunk(0,0);
    stage_chunk(1,1);
    stage_chunk(2,2);

    for (int c=0; c<nch; c++){
        const int st = c & 3;
        if      (c+2 < nch) asm volatile("cp.async.wait_group 2;");
        else if (c+1 < nch) asm volatile("cp.async.wait_group 1;");
        else                asm volatile("cp.async.wait_group 0;");
        __syncthreads();
        if (c+3 < nch) stage_chunk(c+3, (c+3)&3);

        const uint32_t base = sb + (uint32_t)st*STGB;
#pragma unroll
        for (int ks=0; ks<2; ks++){
            uint32_t bh[4][2];
#pragma unroll
            for (int jp=0; jp<2; jp++){
                uint32_t r4[4];
                const uint32_t addrB = base + BOFF
                    + (uint32_t)(n0w + jp*16 + b_ro)*64u
                    + (uint32_t)(((ks*2 + b_kh) ^ b_sw)<<4);
                ldsm4(r4, addrB);
                bh[2*jp  ][0] = r4[0]; bh[2*jp  ][1] = r4[1];
                bh[2*jp+1][0] = r4[2]; bh[2*jp+1][1] = r4[3];
            }
#pragma unroll
            for (int i=0;i<4;i++){
                const uint32_t addrA = base
                    + (uint32_t)(m0w + i*16 + a_ro)*64u
                    + (uint32_t)(((ks*2 + a_kh) ^ a_sw)<<4);
                uint32_t ah[4];
                ldsm4(ah, addrA);
                uint32_t al[4];
                if (SPLITA==2) ldsm4(al, addrA + 8192u);
#pragma unroll
                for (int j=0;j<4;j++){
                    mma_f16(acc[i][j], ah, bh[j]);
                    if (SPLITA==2) mma_f16(acc[i][j], al, bh[j]);
                }
            }
        }
    }

    // ---- epilogue ----
#pragma unroll
    for (int i=0;i<4;i++){
        const long long r0 = m0 + m0w + i*16 + g;
        const long long r1 = r0 + 8;
#pragma unroll
        for (int j=0;j<4;j++){
            const int col = n0 + n0w + j*8 + 2*t;
            if (col < Nst){
                float b0=0.f, b1=0.f;
                if (bias){ b0 = bias[col]; b1 = bias[col+1]; }
                float c0 = acc[i][j][0]*alpha + b0;
                float c1 = acc[i][j][1]*alpha + b1;
                float c2 = acc[i][j][2]*alpha + b0;
                float c3 = acc[i][j][3]*alpha + b1;
                if (EPI==1){
                    c0 = 0.5f*c0*(1.0f+erff(c0*0.70710678118654752440f));
                    c1 = 0.5f*c1*(1.0f+erff(c1*0.70710678118654752440f));
                    c2 = 0.5f*c2*(1.0f+erff(c2*0.70710678118654752440f));
                    c3 = 0.5f*c3*(1.0f+erff(c3*0.70710678118654752440f));
                }
                if (C){
                    *(float2*)&C[(offC + r0*ldc) + col] = make_float2(c0,c1);
                    *(float2*)&C[(offC + r1*ldc) + col] = make_float2(c2,c3);
                }
                if (Ch){
                    if (Cl){
                        f162 h0,l0,h1,l1;
                        hsplit(c0,h0.x,l0.x); hsplit(c1,h0.y,l0.y);
                        hsplit(c2,h1.x,l1.x); hsplit(c3,h1.y,l1.y);
                        *(f162*)&Ch[(offC + r0*ldc) + col] = h0;
                        *(f162*)&Cl[(offC + r0*ldc) + col] = l0;
                        *(f162*)&Ch[(offC + r1*ldc) + col] = h1;
                        *(f162*)&Cl[(offC + r1*ldc) + col] = l1;
                    } else {
                        *(f162*)&Ch[(offC + r0*ldc) + col] = __floats2half2_rn(c0,c1);
                        *(f162*)&Ch[(offC + r1*ldc) + col] = __floats2half2_rn(c2,c3);
                    }
                }
            }
        }
    }
}

// ---------------- weight rounding -------------------------------------------
__global__ __launch_bounds__(256) void round_kernel(
    const float* __restrict__ in, f16* __restrict__ h, int n)
{
    int i = (blockIdx.x*256 + threadIdx.x)*4;
    if (i < n){
        float4 v = *(const float4*)&in[i];
        *(f162*)&h[i]   = __floats2half2_rn(v.x, v.y);
        *(f162*)&h[i+2] = __floats2half2_rn(v.z, v.w);
    }
}
__global__ __launch_bounds__(256) void round_qkv_kernel(
    const float* __restrict__ in, f16* __restrict__ out, int part)
{
    int i = (blockIdx.x*256 + threadIdx.x)*4;       // over L*H*H
    int l = i / (HH*HH), r = i % (HH*HH);
    long long o = (long long)l*H3*HH + (long long)part*HH*HH + r;
    float4 v = *(const float4*)&in[i];
    *(f162*)&out[o]   = __floats2half2_rn(v.x, v.y);
    *(f162*)&out[o+2] = __floats2half2_rn(v.z, v.w);
}
__global__ __launch_bounds__(256) void bias_concat_kernel(
    const float* __restrict__ bq, const float* __restrict__ bk,
    const float* __restrict__ bv, float* __restrict__ o)
{
    int i = blockIdx.x*256 + threadIdx.x;           // over L*HH
    int l = i/HH, c = i%HH;
    o[(long long)l*H3 + c]        = bq[i];
    o[(long long)l*H3 + HH + c]   = bk[i];
    o[(long long)l*H3 + 2*HH + c] = bv[i];
}
__global__ __launch_bounds__(256) void emb_round_pad_kernel(
    const float* __restrict__ emb, f16* __restrict__ h)
{
    int i = (blockIdx.x*256 + threadIdx.x)*4;
    int row = i >> 10;
    float4 v = make_float4(0.f,0.f,0.f,0.f);
    if (row < VV) v = *(const float4*)&emb[(long long)row*HH + (i & 1023)];
    *(f162*)&h[i]   = __floats2half2_rn(v.x, v.y);
    *(f162*)&h[i+2] = __floats2half2_rn(v.z, v.w);
}

// ---------------- V transpose from qkv slice ---------------------------------
__global__ __launch_bounds__(256) void transpose_v_f16(
    const f16* __restrict__ V, f16* __restrict__ Vth)   // V = qkvh + 2*HH
{
    __shared__ float tbuf[32][33];
    const int bh = blockIdx.z, b = bh >> 2, h = bh & 3;
    const int s0 = blockIdx.x*32, d0 = blockIdx.y*32;
    const int tx = threadIdx.x & 31, ty = threadIdx.x >> 5;
#pragma unroll
    for (int i=0;i<4;i++){
        int r = ty + i*8;
        tbuf[r][tx] = __half2float(V[(long long)(b*SS + s0 + r)*H3 + h*DHEAD + d0 + tx]);
    }
    __syncthreads();
#pragma unroll
    for (int i=0;i<4;i++){
        int r = ty + i*8;
        Vth[(long long)(bh*DHEAD + d0 + r)*SS + s0 + tx] = __float2half(tbuf[tx][r]);
    }
}

// ---------------- reductions -------------------------------------------------
__device__ __forceinline__ float warp_sum(float v){
#pragma unroll
    for(int o=16;o;o>>=1) v += __shfl_xor_sync(0xffffffffu,v,o);
    return v;
}
__device__ __forceinline__ float warp_max(float v){
#pragma unroll
    for(int o=16;o;o>>=1) v = fmaxf(v,__shfl_xor_sync(0xffffffffu,v,o));
    return v;
}
template<int NW>
__device__ __forceinline__ float block_sum(float v, float* sh){
    v = warp_sum(v);
    if((threadIdx.x&31)==0) sh[threadIdx.x>>5]=v;
    __syncthreads();
    float t=0.f;
#pragma unroll
    for(int i=0;i<NW;i++) t+=sh[i];
    __syncthreads();
    return t;
}
template<int NW>
__device__ __forceinline__ float block_max(float v, float* sh){
    v = warp_max(v);
    if((threadIdx.x&31)==0) sh[threadIdx.x>>5]=v;
    __syncthreads();
    float t=-1e30f;
#pragma unroll
    for(int i=0;i<NW;i++) t=fmaxf(t,sh[i]);
    __syncthreads();
    return t;
}

// ---------------- embedding + PE -> f16 pairs --------------------------------
__global__ __launch_bounds__(256) void embed_kernel(
    const int* __restrict__ x, const float* __restrict__ emb,
    f16* __restrict__ zh, f16* __restrict__ zl)
{
    const int row = blockIdx.x;
    const int s = row & (SS-1);
    const int tok = x[row];
    const int c0 = threadIdx.x*4;
    float4 ev = *(const float4*)&emb[(long long)tok*HH + c0];
    float vv[4] = {ev.x, ev.y, ev.z, ev.w};
#pragma unroll
    for(int i=0;i<4;i++){
        int c = c0 + i;
        int half = c >> 1;
        float dv = expf(-(float)(2*half) * (9.210340371976184f/(float)HH));
        float ang = (float)s * dv;
        float pe = (c & 1) ? cosf(ang) : sinf(ang);
        vv[i] += pe;
    }
    f162 h0,l0,h1,l1;
    hsplit(vv[0], h0.x, l0.x); hsplit(vv[1], h0.y, l0.y);
    hsplit(vv[2], h1.x, l1.x); hsplit(vv[3], h1.y, l1.y);
    long long o = (long long)row*HH + c0;
    *(f162*)&zh[o]   = h0;  *(f162*)&zl[o]   = l0;
    *(f162*)&zh[o+2] = h1;  *(f162*)&zl[o+2] = l1;
}

// ---------------- fused residual-add + LayerNorm (pairs) ---------------------
__global__ __launch_bounds__(256) void add_ln_kernel(
    const f16* __restrict__ Xh, const f16* __restrict__ Xl,
    const f16* __restrict__ Rh, const f16* __restrict__ Rl,
    const float* __restrict__ g, const float* __restrict__ b,
    f16* __restrict__ outh, f16* __restrict__ outl)
{
    __shared__ float sh[8];
    const long long row = blockIdx.x;
    const int t = threadIdx.x;
    const long long base = row*HH + t*4;
    f162 xh0 = *(const f162*)&Xh[base], xh1 = *(const f162*)&Xh[base+2];
    f162 xl0 = *(const f162*)&Xl[base], xl1 = *(const f162*)&Xl[base+2];
    f162 rh0 = *(const f162*)&Rh[base], rh1 = *(const f162*)&Rh[base+2];
    f162 rl0 = *(const f162*)&Rl[base], rl1 = *(const f162*)&Rl[base+2];
    float v[4];
    v[0] = __half2float(xh0.x)+__half2float(xl0.x)+__half2float(rh0.x)+__half2float(rl0.x);
    v[1] = __half2float(xh0.y)+__half2float(xl0.y)+__half2float(rh0.y)+__half2float(rl0.y);
    v[2] = __half2float(xh1.x)+__half2float(xl1.x)+__half2float(rh1.x)+__half2float(rl1.x);
    v[3] = __half2float(xh1.y)+__half2float(xl1.y)+__half2float(rh1.y)+__half2float(rl1.y);
    float s=0.f;
#pragma unroll
    for(int i=0;i<4;i++) s+=v[i];
    float mean = block_sum<8>(s, sh) * (1.0f/(float)HH);
    float sq=0.f;
#pragma unroll
    for(int i=0;i<4;i++){ float d=v[i]-mean; sq+=d*d; }
    float var = block_sum<8>(sq, sh) * (1.0f/(float)HH);
    float rstd = rsqrtf(var + 1e-5f);
    float4 gv = *(const float4*)&g[t*4];
    float4 bv = *(const float4*)&b[t*4];
    float o0 = (v[0]-mean)*rstd*gv.x + bv.x;
    float o1 = (v[1]-mean)*rstd*gv.y + bv.y;
    float o2 = (v[2]-mean)*rstd*gv.z + bv.z;
    float o3 = (v[3]-mean)*rstd*gv.w + bv.w;
    f162 h0,l0,h1,l1;
    hsplit(o0,h0.x,l0.x); hsplit(o1,h0.y,l0.y);
    hsplit(o2,h1.x,l1.x); hsplit(o3,h1.y,l1.y);
    *(f162*)&outh[base]   = h0;  *(f162*)&outl[base]   = l0;
    *(f162*)&outh[base+2] = h1;  *(f162*)&outl[base+2] = l1;
}

// ---------------- causal masked softmax (f16 scores) -> P hi + atten_last ----
__global__ __launch_bounds__(128) void attn_softmax_kernel(
    const f16* __restrict__ S, const int* __restrict__ lengths,
    f16* __restrict__ ph, float* __restrict__ attn_out)
{
    __shared__ float sh[4];
    const int idx = blockIdx.x;
    const int q = idx & (SS-1);
    const int b = idx >> 11;
    const f16* srow = S + (long long)idx*SS;
    f16* phr = ph + (long long)idx*SS;
    const int t = threadIdx.x;
    if (q >= lengths[b]) {
#pragma unroll
        for(int i=0;i<4;i++){ int k=t+(i<<7); phr[k] = __float2half(0.f); }
        if (attn_out && t==0) attn_out[idx] = 0.f;
        return;
    }
    float v[4]; float m=-1e30f;
#pragma unroll
    for(int i=0;i<4;i++){
        int k=t+(i<<7);
        v[i] = (k<=q) ? __half2float(srow[k]) : -1e30f;
        m = fmaxf(m,v[i]);
    }
    m = block_max<4>(m, sh);
    float s=0.f;
#pragma unroll
    for(int i=0;i<4;i++){ v[i]=expf(v[i]-m); s+=v[i]; }
    s = block_sum<4>(s, sh);
    float r = 1.0f/s;
#pragma unroll
    for(int i=0;i<4;i++){ int k=t+(i<<7); phr[k] = __float2half(v[i]*r); }
    if (attn_out && t==0) attn_out[idx] = r;
}

// ---------------- vocab softmax ----------------------------------------------
__global__ __launch_bounds__(256) void vocab_softmax_kernel(float* __restrict__ logits)
{
    __shared__ float sh[8];
    const long long row = blockIdx.x;
    float* p = logits + row*VV;
    const int t = threadIdx.x;
    float v[32]; float m=-1e30f;
#pragma unroll
    for(int i=0;i<32;i++){ int k=t+(i<<8); v[i]=(k<VV)?p[k]:-1e30f; m=fmaxf(m,v[i]); }
    m = block_max<8>(m, sh);
    float s=0.f;
#pragma unroll
    for(int i=0;i<32;i++){ v[i]=expf(v[i]-m); s+=v[i]; }
    s = block_sum<8>(s, sh);
    float r = 1.0f/s;
#pragma unroll
    for(int i=0;i<32;i++){ int k=t+(i<<8); if(k<VV) p[k]=v[i]*r; }
}

// ---------------- host-side launch helper ------------------------------------
static void launch_tgemm(const f16*Ah,const f16*Al,const f16*Bh,
    const float*bias, float*C, f16*Ch, f16*Cl,
    int M,int N,int K,int lda,int ldb,int ldc,float alpha,int Nst,
    bool gelu_ep,int splita,int causal,int triK,
    int batch,int divz,long long sA1,long long sA2,long long sB1,long long sB2,
    long long sC1,long long sC2)
{
    cudaFuncSetAttribute(tgemm<0,2>, cudaFuncAttributeMaxDynamicSharedMemorySize, 4*24576);
    cudaFuncSetAttribute(tgemm<1,1>, cudaFuncAttributeMaxDynamicSharedMemorySize, 4*16384);
    cudaFuncSetAttribute(tgemm<0,1>, cudaFuncAttributeMaxDynamicSharedMemorySize, 4*16384);
    dim3 grid(N/128, M/128, batch);
    if (causal){
        const int nt = M/128;                      // lower-triangle pairs
        grid = dim3(nt*(nt+1)/2, 1, batch);
    }
    const int smem = 4*((splita==2)?24576:16384);
    if (splita==1){
        if (gelu_ep)
            tgemm<1,1><<<grid,256,smem>>>(Ah,Al,Bh,bias,C,Ch,Cl,M,N,K,lda,ldb,ldc,alpha,Nst,causal,triK,divz,sA1,sA2,sB1,sB2,sC1,sC2);
        else
            tgemm<0,1><<<grid,256,smem>>>(Ah,Al,Bh,bias,C,Ch,Cl,M,N,K,lda,ldb,ldc,alpha,Nst,causal,triK,divz,sA1,sA2,sB1,sB2,sC1,sC2);
    } else {
        tgemm<0,2><<<grid,256,smem>>>(Ah,Al,Bh,bias,C,Ch,Cl,M,N,K,lda,ldb,ldc,alpha,Nst,causal,triK,divz,sA1,sA2,sB1,sB2,sC1,sC2);
    }
}

#define GETSYM(var, sym) cudaGetSymbolAddress((void**)&var, sym)

extern "C" void kernel_launch(void* const* d_in, const int* in_sizes, int n_in,
                              void* d_out, int out_size)
{
    const int*   x       = (const int*)  d_in[0];
    const int*   lengths = (const int*)  d_in[1];
    const float* emb     = (const float*)d_in[2];
    const float* Wq = (const float*)d_in[3];
    const float* bq = (const float*)d_in[4];
    const float* Wk = (const float*)d_in[5];
    const float* bk = (const float*)d_in[6];
    const float* Wv = (const float*)d_in[7];
    const float* bv = (const float*)d_in[8];
    const float* W1 = (const float*)d_in[9];
    const float* b1 = (const float*)d_in[10];
    const float* W2 = (const float*)d_in[11];
    const float* b2 = (const float*)d_in[12];
    const float* g1 = (const float*)d_in[13];
    const float* be1= (const float*)d_in[14];
    const float* g2 = (const float*)d_in[15];
    const float* be2= (const float*)d_in[16];
    const float* Wfc= (const float*)d_in[17];
    const float* bfc= (const float*)d_in[18];
    float* out      = (float*)d_out;
    float* attn_out = out + (long long)NB*SS*VV;

    float *bqkv;
    GETSYM(bqkv,g_bqkv);
    f16 *sh16,*zh,*zl,*z1h,*z1l,*qkvh,*qkvl,*fh,*och,*ocl,*ph,*vth;
    GETSYM(sh16,g_sh);
    GETSYM(zh,g_zh); GETSYM(zl,g_zl); GETSYM(z1h,g_z1h); GETSYM(z1l,g_z1l);
    GETSYM(qkvh,g_qkvh); GETSYM(qkvl,g_qkvl); GETSYM(fh,g_fh);
    GETSYM(och,g_och); GETSYM(ocl,g_ocl); GETSYM(ph,g_ph); GETSYM(vth,g_vth);
    f16 *Wqkvh,*W1h,*W2h,*Wfh,*emh;
    GETSYM(Wqkvh,g_Wqkvh); GETSYM(W1h,g_W1h); GETSYM(W2h,g_W2h);
    GETSYM(Wfh,g_Wfh); GETSYM(emh,g_emh);

    const long long S3  = (long long)SS*H3;
    const long long SS2 = (long long)SS*SS;
    const long long SD  = (long long)SS*DHEAD;
    const int WN = LLAY*HH*HH;

    // ---- pack + round weights ----
    round_qkv_kernel<<<WN/1024,256>>>(Wq, Wqkvh, 0);
    round_qkv_kernel<<<WN/1024,256>>>(Wk, Wqkvh, 1);
    round_qkv_kernel<<<WN/1024,256>>>(Wv, Wqkvh, 2);
    bias_concat_kernel<<<LLAY*HH/256,256>>>(bq, bk, bv, bqkv);
    round_kernel<<<WN/1024,256>>>(W1, W1h, WN);
    round_kernel<<<WN/1024,256>>>(W2, W2h, WN);
    round_kernel<<<HH*HH/1024,256>>>(Wfc, Wfh, HH*HH);
    emb_round_pad_kernel<<<VPAD*HH/1024,256>>>(emb, emh);

    embed_kernel<<<NTOK,256>>>(x, emb, zh, zl);

    for (int l=0;l<LLAY;l++){
        const long long wo3 = (long long)l*H3*HH;
        const long long wo  = (long long)l*HH*HH;
        const bool last = (l==LLAY-1);

        // fused QKV: [8192,3072] = z @ Wqkv^T + bqkv; pairs only for last layer
        launch_tgemm(zh,zl, Wqkvh+wo3, bqkv+(long long)l*H3, nullptr,
                     qkvh, last?qkvl:nullptr,
                     NTOK,H3,HH, HH,HH,H3, 1.f,H3,false,1,0,0, 1,1,0,0,0,0,0,0);

        // V -> Vt [bh][dh][S] from qkv slice
        {
            dim3 gr(SS/32, DHEAD/32, NB*NHEADS);
            transpose_v_f16<<<gr,256>>>(qkvh + 2*HH, vth);
        }

        // scores: Q@K^T/32 -> f16, compact causal grid; split Q on last layer
        launch_tgemm(qkvh, qkvl, qkvh+HH, nullptr, nullptr, sh16, nullptr,
                     SS,SS,DHEAD, H3,H3,SS, 1.0f/32.0f,SS,false, last?2:1, 1, 0,
                     NB*NHEADS, NHEADS, S3, DHEAD, S3, DHEAD,
                     (long long)NHEADS*SS2, SS2);

        attn_softmax_kernel<<<NB*NHEADS*SS,128>>>(sh16, lengths, ph,
                                                  last?attn_out:nullptr);

        // O = P @ Vt^T, triangular K skip (heavy-first tile order), out pairs
        launch_tgemm(ph,ph, vth, nullptr, nullptr, och, ocl,
                     SS,DHEAD,SS, SS,SS,DHEAD, 1.f,DHEAD,false,1,0,1,
                     NB*NHEADS, 1, SS2, 0, SD, 0, SD, 0);

        add_ln_kernel<<<NTOK,256>>>(zh,zl, och,ocl, g1+l*HH, be1+l*HH, z1h, z1l);

        // FFN (A hi-only; FFN1 out hi-only)
        launch_tgemm(z1h,z1h, W1h+wo, b1+l*HH, nullptr, fh, nullptr,
                     NTOK,HH,HH, HH,HH,HH, 1.f,HH,true,1,0,0, 1,1,0,0,0,0,0,0);
        launch_tgemm(fh,fh, W2h+wo, b2+l*HH, nullptr, och, ocl,
                     NTOK,HH,HH, HH,HH,HH, 1.f,HH,false,1,0,0, 1,1,0,0,0,0,0,0);

        add_ln_kernel<<<NTOK,256>>>(z1h,z1l, och,ocl, g2+l*HH, be2+l*HH, zh, zl);
    }

    // out_fc = z @ Wfc^T + bfc (A split) -> pairs
    launch_tgemm(zh,zl, Wfh, bfc, nullptr, och, ocl,
                 NTOK,HH,HH, HH,HH,HH, 1.f,HH,false,2,0,0, 1,1,0,0,0,0,0,0);
    // logits = out_fc @ emb^T, A hi-only
    launch_tgemm(och,och, emh, nullptr, out, nullptr, nullptr,
                 NTOK,VPAD,HH, HH,HH,VV, 1.f,VV,false,1,0,0, 1,1,0,0,0,0,0,0);
    vocab_softmax_kernel<<<NTOK,256>>>(out);
}

// round 17
// speedup vs baseline: 1.0478x; 1.0041x over previous
#include <cuda_runtime.h>
#include <cuda_fp16.h>
#include <math.h>
#include <stdint.h>

#define NB     16
#define SS     512
#define HH     1024
#define H3     (3*HH)
#define VV     8000
#define VPAD   8064
#define LLAY   8
#define NHEADS 4
#define DHEAD  256
#define NTOK   (NB*SS)

typedef __half  f16;
typedef __half2 f162;

// ---------------- scratch (__device__ globals) --------------------------------
__device__ f16 g_sh  [NB*NHEADS*SS*SS];           // attention scores f16
__device__ f16 g_zh  [NTOK*HH],  g_zl [NTOK*HH];  // residual stream pairs
__device__ f16 g_z1h [NTOK*HH],  g_z1l[NTOK*HH];
__device__ f16 g_qkvh[NTOK*H3],  g_qkvl[NTOK*H3]; // fused QKV out (lo: layer7 only)
__device__ f16 g_fh  [NTOK*HH];                   // FFN1 out (hi only)
__device__ f16 g_och [NTOK*HH],  g_ocl[NTOK*HH];  // attn-out / FFN2-out / fc-out pairs
__device__ f16 g_ph  [NB*NHEADS*SS*SS];           // P hi only
__device__ f16 g_vth [NTOK*HH];                   // V^T [bh][dh][S]
__device__ f16 g_Wqkvh[LLAY*H3*HH];
__device__ f16 g_W1h[LLAY*HH*HH];
__device__ f16 g_W2h[LLAY*HH*HH];
__device__ f16 g_Wfh[HH*HH];
__device__ f16 g_emh[VPAD*HH];
__device__ float g_bqkv[LLAY*H3];

// ---------------- helpers -----------------------------------------------------
__device__ __forceinline__ void hsplit(float x, f16& h, f16& l){
    h = __float2half(x);
    l = __float2half(x - __half2float(h));
}
__device__ __forceinline__ void mma_f16(float* c, const uint32_t* a, const uint32_t* b){
    asm volatile("mma.sync.aligned.m16n8k16.row.col.f32.f16.f16.f32 "
        "{%0,%1,%2,%3}, {%4,%5,%6,%7}, {%8,%9}, {%0,%1,%2,%3};"
        : "+f"(c[0]),"+f"(c[1]),"+f"(c[2]),"+f"(c[3])
        : "r"(a[0]),"r"(a[1]),"r"(a[2]),"r"(a[3]), "r"(b[0]),"r"(b[1]));
}
__device__ __forceinline__ void ldsm4(uint32_t* r, uint32_t addr){
    asm volatile("ldmatrix.sync.aligned.m8n8.x4.shared.b16 {%0,%1,%2,%3}, [%4];"
        : "=r"(r[0]),"=r"(r[1]),"=r"(r[2]),"=r"(r[3]) : "r"(addr));
}
__device__ __forceinline__ uint32_t s2u(const void* p){
    uint32_t a;
    asm("{ .reg .u64 t; cvta.to.shared.u64 t, %1; cvt.u32.u64 %0, t; }" : "=r"(a) : "l"(p));
    return a;
}
__device__ __forceinline__ void cp16(uint32_t dst, const void* src){
    asm volatile("cp.async.cg.shared.global [%0], [%1], 16;" :: "r"(dst), "l"(src));
}

// ================= fp16 NT GEMM: ldmatrix, cp.async deep pipeline =============
// SPLITA=2: A = Ah+Al (4 stages); SPLITA=1: A hi only (6 stages). 128x128x32.
// causal!=0: compact lower-triangle grid (blockIdx.x = pair id); optional
//            per-batch row-skip via lens (skip tile if m0 >= lens[z/divz]).
// triK!=0:  effective K = m0+128, heavy-first tile order.
template<int EPI, int SPLITA>
__global__ void __launch_bounds__(256,2) tgemm(
    const f16* __restrict__ Ah, const f16* __restrict__ Al,
    const f16* __restrict__ Bh,
    const float* __restrict__ bias,
    float* __restrict__ C, f16* __restrict__ Ch, f16* __restrict__ Cl,
    int M, int N, int K, int lda, int ldb, int ldc, float alpha, int Nst,
    int causal, int triK, const int* __restrict__ lens,
    int divz, long long sA1, long long sA2, long long sB1, long long sB2,
    long long sC1, long long sC2)
{
    constexpr uint32_t STGB = (SPLITA==2) ? 24576u : 16384u;
    constexpr uint32_t BOFF = (SPLITA==2) ? 16384u : 8192u;
    constexpr int NS = (SPLITA==2) ? 4 : 6;
    extern __shared__ char smem[];

    const int z = blockIdx.z;
    int m0, n0;
    if (causal){
        const int p = blockIdx.x;
        const int mi = (p>=6) ? 3 : (p>=3) ? 2 : (p>=1) ? 1 : 0;
        const int ni = p - ((mi*(mi+1))>>1);
        m0 = mi*128; n0 = ni*128;
        if (lens && m0 >= lens[z/divz]) return;   // rows q>=len are overwritten by softmax
    } else if (triK){
        m0 = (gridDim.y - 1 - blockIdx.y)*128;    // heavy tiles first
        n0 = blockIdx.x*128;
    } else {
        m0 = blockIdx.y*128; n0 = blockIdx.x*128;
    }

    const long long offA = (long long)(z/divz)*sA1 + (long long)(z%divz)*sA2;
    const long long offB = (long long)(z/divz)*sB1 + (long long)(z%divz)*sB2;
    const long long offC = (long long)(z/divz)*sC1 + (long long)(z%divz)*sC2;
    Ah += offA; Al += offA; Bh += offB;

    const int tid = threadIdx.x;
    const int wid = tid>>5, lane = tid&31;
    const int g = lane>>2, t = lane&3;
    const int m0w = (wid&1)*64, n0w = (wid>>1)*32;

    const int a_ro = ((lane>>3)&1)*8 + (lane&7);
    const int a_kh = lane>>4;
    const int a_sw = (a_ro>>1)&3;
    const int b_ro = (lane>>4)*8 + (lane&7);
    const int b_kh = (lane>>3)&1;
    const int b_sw = (b_ro>>1)&3;

    const uint32_t sb = s2u(smem);
    const int srow = tid>>2;
    const int sch  = tid&3;
    const uint32_t soff0 = (uint32_t)(srow*64 + ((sch  ^ ((srow>>1)&3))<<4));
    const int srow1 = (tid+256)>>2;
    const uint32_t soff1 = (uint32_t)(srow1*64 + ((sch ^ ((srow1>>1)&3))<<4));

    float acc[4][4][4];
#pragma unroll
    for (int i=0;i<4;i++)
#pragma unroll
        for (int j=0;j<4;j++)
#pragma unroll
            for (int r=0;r<4;r++) acc[i][j][r]=0.f;

    const int Keff = triK ? (m0 + 128) : K;
    const int nch = Keff >> 5;

    auto stage_chunk = [&](int c, int st){
        const uint32_t base = sb + (uint32_t)st*STGB;
        const int kc = c*32;
        {
            const long long ga = (long long)(m0+srow)*lda + kc + sch*8;
            const long long gb = (long long)(n0+srow)*ldb + kc + sch*8;
            cp16(base +        soff0, Ah + ga);
            if (SPLITA==2) cp16(base + 8192 + soff0, Al + ga);
            cp16(base + BOFF + soff0, Bh + gb);
        }
        {
            const long long ga = (long long)(m0+srow1)*lda + kc + sch*8;
            const long long gb = (long long)(n0+srow1)*ldb + kc + sch*8;
            cp16(base +        soff1, Ah + ga);
            if (SPLITA==2) cp16(base + 8192 + soff1, Al + ga);
            cp16(base + BOFF + soff1, Bh + gb);
        }
        asm volatile("cp.async.commit_group;");
    };

    // prologue: stage first NS-1 chunks (all nch >= NS here)
#pragma unroll
    for (int c=0;c<NS-1;c++) stage_chunk(c, c);

    int st = 0;                       // c % NS
    int sl = NS-1;                    // (c+NS-1) % NS
    for (int c=0; c<nch; c++){
        // wait until chunk c's group is retired (FIFO retire order)
        if (NS==6){
            if      (c+4 < nch) asm volatile("cp.async.wait_group 4;");
            else if (c+3 < nch) asm volatile("cp.async.wait_group 3;");
            else if (c+2 < nch) asm volatile("cp.async.wait_group 2;");
            else if (c+1 < nch) asm volatile("cp.async.wait_group 1;");
            else                asm volatile("cp.async.wait_group 0;");
        } else {
            if      (c+2 < nch) asm volatile("cp.async.wait_group 2;");
            else if (c+1 < nch) asm volatile("cp.async.wait_group 1;");
            else                asm volatile("cp.async.wait_group 0;");
        }
        __syncthreads();
        if (c+NS-1 < nch) stage_chunk(c+NS-1, sl);   // slot (c-1)%NS: safe

        const uint32_t base = sb + (uint32_t)st*STGB;
#pragma unroll
        for (int ks=0; ks<2; ks++){
            uint32_t bh[4][2];
#pragma unroll
            for (int jp=0; jp<2; jp++){
                uint32_t r4[4];
                const uint32_t addrB = base + BOFF
                    + (uint32_t)(n0w + jp*16 + b_ro)*64u
                    + (uint32_t)(((ks*2 + b_kh) ^ b_sw)<<4);
                ldsm4(r4, addrB);
                bh[2*jp  ][0] = r4[0]; bh[2*jp  ][1] = r4[1];
                bh[2*jp+1][0] = r4[2]; bh[2*jp+1][1] = r4[3];
            }
#pragma unroll
            for (int i=0;i<4;i++){
                const uint32_t addrA = base
                    + (uint32_t)(m0w + i*16 + a_ro)*64u
                    + (uint32_t)(((ks*2 + a_kh) ^ a_sw)<<4);
                uint32_t ah[4];
                ldsm4(ah, addrA);
                uint32_t al[4];
                if (SPLITA==2) ldsm4(al, addrA + 8192u);
#pragma unroll
                for (int j=0;j<4;j++){
                    mma_f16(acc[i][j], ah, bh[j]);
                    if (SPLITA==2) mma_f16(acc[i][j], al, bh[j]);
                }
            }
        }
        if (++st == NS) st = 0;
        if (++sl == NS) sl = 0;
    }

    // ---- epilogue ----
#pragma unroll
    for (int i=0;i<4;i++){
        const long long r0 = m0 + m0w + i*16 + g;
        const long long r1 = r0 + 8;
#pragma unroll
        for (int j=0;j<4;j++){
            const int col = n0 + n0w + j*8 + 2*t;
            if (col < Nst){
                float b0=0.f, b1=0.f;
                if (bias){ b0 = bias[col]; b1 = bias[col+1]; }
                float c0 = acc[i][j][0]*alpha + b0;
                float c1 = acc[i][j][1]*alpha + b1;
                float c2 = acc[i][j][2]*alpha + b0;
                float c3 = acc[i][j][3]*alpha + b1;
                if (EPI==1){
                    c0 = 0.5f*c0*(1.0f+erff(c0*0.70710678118654752440f));
                    c1 = 0.5f*c1*(1.0f+erff(c1*0.70710678118654752440f));
                    c2 = 0.5f*c2*(1.0f+erff(c2*0.70710678118654752440f));
                    c3 = 0.5f*c3*(1.0f+erff(c3*0.70710678118654752440f));
                }
                if (C){
                    *(float2*)&C[(offC + r0*ldc) + col] = make_float2(c0,c1);
                    *(float2*)&C[(offC + r1*ldc) + col] = make_float2(c2,c3);
                }
                if (Ch){
                    if (Cl){
                        f162 h0,l0,h1,l1;
                        hsplit(c0,h0.x,l0.x); hsplit(c1,h0.y,l0.y);
                        hsplit(c2,h1.x,l1.x); hsplit(c3,h1.y,l1.y);
                        *(f162*)&Ch[(offC + r0*ldc) + col] = h0;
                        *(f162*)&Cl[(offC + r0*ldc) + col] = l0;
                        *(f162*)&Ch[(offC + r1*ldc) + col] = h1;
                        *(f162*)&Cl[(offC + r1*ldc) + col] = l1;
                    } else {
                        *(f162*)&Ch[(offC + r0*ldc) + col] = __floats2half2_rn(c0,c1);
                        *(f162*)&Ch[(offC + r1*ldc) + col] = __floats2half2_rn(c2,c3);
                    }
                }
            }
        }
    }
}

// ---------------- weight rounding -------------------------------------------
__global__ __launch_bounds__(256) void round_kernel(
    const float* __restrict__ in, f16* __restrict__ h, int n)
{
    int i = (blockIdx.x*256 + threadIdx.x)*4;
    if (i < n){
        float4 v = *(const float4*)&in[i];
        *(f162*)&h[i]   = __floats2half2_rn(v.x, v.y);
        *(f162*)&h[i+2] = __floats2half2_rn(v.z, v.w);
    }
}
__global__ __launch_bounds__(256) void round_qkv_kernel(
    const float* __restrict__ in, f16* __restrict__ out, int part)
{
    int i = (blockIdx.x*256 + threadIdx.x)*4;       // over L*H*H
    int l = i / (HH*HH), r = i % (HH*HH);
    long long o = (long long)l*H3*HH + (long long)part*HH*HH + r;
    float4 v = *(const float4*)&in[i];
    *(f162*)&out[o]   = __floats2half2_rn(v.x, v.y);
    *(f162*)&out[o+2] = __floats2half2_rn(v.z, v.w);
}
__global__ __launch_bounds__(256) void bias_concat_kernel(
    const float* __restrict__ bq, const float* __restrict__ bk,
    const float* __restrict__ bv, float* __restrict__ o)
{
    int i = blockIdx.x*256 + threadIdx.x;           // over L*HH
    int l = i/HH, c = i%HH;
    o[(long long)l*H3 + c]        = bq[i];
    o[(long long)l*H3 + HH + c]   = bk[i];
    o[(long long)l*H3 + 2*HH + c] = bv[i];
}
__global__ __launch_bounds__(256) void emb_round_pad_kernel(
    const float* __restrict__ emb, f16* __restrict__ h)
{
    int i = (blockIdx.x*256 + threadIdx.x)*4;
    int row = i >> 10;
    float4 v = make_float4(0.f,0.f,0.f,0.f);
    if (row < VV) v = *(const float4*)&emb[(long long)row*HH + (i & 1023)];
    *(f162*)&h[i]   = __floats2half2_rn(v.x, v.y);
    *(f162*)&h[i+2] = __floats2half2_rn(v.z, v.w);
}

// ---------------- V transpose from qkv slice ---------------------------------
__global__ __launch_bounds__(256) void transpose_v_f16(
    const f16* __restrict__ V, f16* __restrict__ Vth)   // V = qkvh + 2*HH
{
    __shared__ float tbuf[32][33];
    const int bh = blockIdx.z, b = bh >> 2, h = bh & 3;
    const int s0 = blockIdx.x*32, d0 = blockIdx.y*32;
    const int tx = threadIdx.x & 31, ty = threadIdx.x >> 5;
#pragma unroll
    for (int i=0;i<4;i++){
        int r = ty + i*8;
        tbuf[r][tx] = __half2float(V[(long long)(b*SS + s0 + r)*H3 + h*DHEAD + d0 + tx]);
    }
    __syncthreads();
#pragma unroll
    for (int i=0;i<4;i++){
        int r = ty + i*8;
        Vth[(long long)(bh*DHEAD + d0 + r)*SS + s0 + tx] = __float2half(tbuf[tx][r]);
    }
}

// ---------------- reductions -------------------------------------------------
__device__ __forceinline__ float warp_sum(float v){
#pragma unroll
    for(int o=16;o;o>>=1) v += __shfl_xor_sync(0xffffffffu,v,o);
    return v;
}
__device__ __forceinline__ float warp_max(float v){
#pragma unroll
    for(int o=16;o;o>>=1) v = fmaxf(v,__shfl_xor_sync(0xffffffffu,v,o));
    return v;
}
template<int NW>
__device__ __forceinline__ float block_sum(float v, float* sh){
    v = warp_sum(v);
    if((threadIdx.x&31)==0) sh[threadIdx.x>>5]=v;
    __syncthreads();
    float t=0.f;
#pragma unroll
    for(int i=0;i<NW;i++) t+=sh[i];
    __syncthreads();
    return t;
}
template<int NW>
__device__ __forceinline__ float block_max(float v, float* sh){
    v = warp_max(v);
    if((threadIdx.x&31)==0) sh[threadIdx.x>>5]=v;
    __syncthreads();
    float t=-1e30f;
#pragma unroll
    for(int i=0;i<NW;i++) t=fmaxf(t,sh[i]);
    __syncthreads();
    return t;
}

// ---------------- embedding + PE -> f16 pairs --------------------------------
__global__ __launch_bounds__(256) void embed_kernel(
    const int* __restrict__ x, const float* __restrict__ emb,
    f16* __restrict__ zh, f16* __restrict__ zl)
{
    const int row = blockIdx.x;
    const int s = row & (SS-1);
    const int tok = x[row];
    const int c0 = threadIdx.x*4;
    float4 ev = *(const float4*)&emb[(long long)tok*HH + c0];
    float vv[4] = {ev.x, ev.y, ev.z, ev.w};
#pragma unroll
    for(int i=0;i<4;i++){
        int c = c0 + i;
        int half = c >> 1;
        float dv = expf(-(float)(2*half) * (9.210340371976184f/(float)HH));
        float ang = (float)s * dv;
        float pe = (c & 1) ? cosf(ang) : sinf(ang);
        vv[i] += pe;
    }
    f162 h0,l0,h1,l1;
    hsplit(vv[0], h0.x, l0.x); hsplit(vv[1], h0.y, l0.y);
    hsplit(vv[2], h1.x, l1.x); hsplit(vv[3], h1.y, l1.y);
    long long o = (long long)row*HH + c0;
    *(f162*)&zh[o]   = h0;  *(f162*)&zl[o]   = l0;
    *(f162*)&zh[o+2] = h1;  *(f162*)&zl[o+2] = l1;
}

// ---------------- fused residual-add + LayerNorm (pairs) ---------------------
__global__ __launch_bounds__(256) void add_ln_kernel(
    const f16* __restrict__ Xh, const f16* __restrict__ Xl,
    const f16* __restrict__ Rh, const f16* __restrict__ Rl,
    const float* __restrict__ g, const float* __restrict__ b,
    f16* __restrict__ outh, f16* __restrict__ outl)
{
    __shared__ float sh[8];
    const long long row = blockIdx.x;
    const int t = threadIdx.x;
    const long long base = row*HH + t*4;
    f162 xh0 = *(const f162*)&Xh[base], xh1 = *(const f162*)&Xh[base+2];
    f162 xl0 = *(const f162*)&Xl[base], xl1 = *(const f162*)&Xl[base+2];
    f162 rh0 = *(const f162*)&Rh[base], rh1 = *(const f162*)&Rh[base+2];
    f162 rl0 = *(const f162*)&Rl[base], rl1 = *(const f162*)&Rl[base+2];
    float v[4];
    v[0] = __half2float(xh0.x)+__half2float(xl0.x)+__half2float(rh0.x)+__half2float(rl0.x);
    v[1] = __half2float(xh0.y)+__half2float(xl0.y)+__half2float(rh0.y)+__half2float(rl0.y);
    v[2] = __half2float(xh1.x)+__half2float(xl1.x)+__half2float(rh1.x)+__half2float(rl1.x);
    v[3] = __half2float(xh1.y)+__half2float(xl1.y)+__half2float(rh1.y)+__half2float(rl1.y);
    float s=0.f;
#pragma unroll
    for(int i=0;i<4;i++) s+=v[i];
    float mean = block_sum<8>(s, sh) * (1.0f/(float)HH);
    float sq=0.f;
#pragma unroll
    for(int i=0;i<4;i++){ float d=v[i]-mean; sq+=d*d; }
    float var = block_sum<8>(sq, sh) * (1.0f/(float)HH);
    float rstd = rsqrtf(var + 1e-5f);
    float4 gv = *(const float4*)&g[t*4];
    float4 bv = *(const float4*)&b[t*4];
    float o0 = (v[0]-mean)*rstd*gv.x + bv.x;
    float o1 = (v[1]-mean)*rstd*gv.y + bv.y;
    float o2 = (v[2]-mean)*rstd*gv.z + bv.z;
    float o3 = (v[3]-mean)*rstd*gv.w + bv.w;
    f162 h0,l0,h1,l1;
    hsplit(o0,h0.x,l0.x); hsplit(o1,h0.y,l0.y);
    hsplit(o2,h1.x,l1.x); hsplit(o3,h1.y,l1.y);
    *(f162*)&outh[base]   = h0;  *(f162*)&outl[base]   = l0;
    *(f162*)&outh[base+2] = h1;  *(f162*)&outl[base+2] = l1;
}

// ---------------- causal masked softmax (f16 scores) -> P hi + atten_last ----
__global__ __launch_bounds__(128) void attn_softmax_kernel(
    const f16* __restrict__ S, const int* __restrict__ lengths,
    f16* __restrict__ ph, float* __restrict__ attn_out)
{
    __shared__ float sh[4];
    const int idx = blockIdx.x;
    const int q = idx & (SS-1);
    const int b = idx >> 11;
    const f16* srow = S + (long long)idx*SS;
    f16* phr = ph + (long long)idx*SS;
    const int t = threadIdx.x;
    if (q >= lengths[b]) {
#pragma unroll
        for(int i=0;i<4;i++){ int k=t+(i<<7); phr[k] = __float2half(0.f); }
        if (attn_out && t==0) attn_out[idx] = 0.f;
        return;
    }
    float v[4]; float m=-1e30f;
#pragma unroll
    for(int i=0;i<4;i++){
        int k=t+(i<<7);
        v[i] = (k<=q) ? __half2float(srow[k]) : -1e30f;
        m = fmaxf(m,v[i]);
    }
    m = block_max<4>(m, sh);
    float s=0.f;
#pragma unroll
    for(int i=0;i<4;i++){ v[i]=expf(v[i]-m); s+=v[i]; }
    s = block_sum<4>(s, sh);
    float r = 1.0f/s;
#pragma unroll
    for(int i=0;i<4;i++){ int k=t+(i<<7); phr[k] = __float2half(v[i]*r); }
    if (attn_out && t==0) attn_out[idx] = r;
}

// ---------------- vocab softmax ----------------------------------------------
__global__ __launch_bounds__(256) void vocab_softmax_kernel(float* __restrict__ logits)
{
    __shared__ float sh[8];
    const long long row = blockIdx.x;
    float* p = logits + row*VV;
    const int t = threadIdx.x;
    float v[32]; float m=-1e30f;
#pragma unroll
    for(int i=0;i<32;i++){ int k=t+(i<<8); v[i]=(k<VV)?p[k]:-1e30f; m=fmaxf(m,v[i]); }
    m = block_max<8>(m, sh);
    float s=0.f;
#pragma unroll
    for(int i=0;i<32;i++){ v[i]=expf(v[i]-m); s+=v[i]; }
    s = block_sum<8>(s, sh);
    float r = 1.0f/s;
#pragma unroll
    for(int i=0;i<32;i++){ int k=t+(i<<8); if(k<VV) p[k]=v[i]*r; }
}

// ---------------- host-side launch helper ------------------------------------
static void launch_tgemm(const f16*Ah,const f16*Al,const f16*Bh,
    const float*bias, float*C, f16*Ch, f16*Cl,
    int M,int N,int K,int lda,int ldb,int ldc,float alpha,int Nst,
    bool gelu_ep,int splita,int causal,int triK,const int*lens,
    int batch,int divz,long long sA1,long long sA2,long long sB1,long long sB2,
    long long sC1,long long sC2)
{
    cudaFuncSetAttribute(tgemm<0,2>, cudaFuncAttributeMaxDynamicSharedMemorySize, 4*24576);
    cudaFuncSetAttribute(tgemm<1,1>, cudaFuncAttributeMaxDynamicSharedMemorySize, 6*16384);
    cudaFuncSetAttribute(tgemm<0,1>, cudaFuncAttributeMaxDynamicSharedMemorySize, 6*16384);
    dim3 grid(N/128, M/128, batch);
    if (causal){
        const int nt = M/128;                      // lower-triangle pairs
        grid = dim3(nt*(nt+1)/2, 1, batch);
    }
    const int smem = (splita==2) ? 4*24576 : 6*16384;
    if (splita==1){
        if (gelu_ep)
            tgemm<1,1><<<grid,256,smem>>>(Ah,Al,Bh,bias,C,Ch,Cl,M,N,K,lda,ldb,ldc,alpha,Nst,causal,triK,lens,divz,sA1,sA2,sB1,sB2,sC1,sC2);
        else
            tgemm<0,1><<<grid,256,smem>>>(Ah,Al,Bh,bias,C,Ch,Cl,M,N,K,lda,ldb,ldc,alpha,Nst,causal,triK,lens,divz,sA1,sA2,sB1,sB2,sC1,sC2);
    } else {
        tgemm<0,2><<<grid,256,smem>>>(Ah,Al,Bh,bias,C,Ch,Cl,M,N,K,lda,ldb,ldc,alpha,Nst,causal,triK,lens,divz,sA1,sA2,sB1,sB2,sC1,sC2);
    }
}

#define GETSYM(var, sym) cudaGetSymbolAddress((void**)&var, sym)

extern "C" void kernel_launch(void* const* d_in, const int* in_sizes, int n_in,
                              void* d_out, int out_size)
{
    const int*   x       = (const int*)  d_in[0];
    const int*   lengths = (const int*)  d_in[1];
    const float* emb     = (const float*)d_in[2];
    const float* Wq = (const float*)d_in[3];
    const float* bq = (const float*)d_in[4];
    const float* Wk = (const float*)d_in[5];
    const float* bk = (const float*)d_in[6];
    const float* Wv = (const float*)d_in[7];
    const float* bv = (const float*)d_in[8];
    const float* W1 = (const float*)d_in[9];
    const float* b1 = (const float*)d_in[10];
    const float* W2 = (const float*)d_in[11];
    const float* b2 = (const float*)d_in[12];
    const float* g1 = (const float*)d_in[13];
    const float* be1= (const float*)d_in[14];
    const float* g2 = (const float*)d_in[15];
    const float* be2= (const float*)d_in[16];
    const float* Wfc= (const float*)d_in[17];
    const float* bfc= (const float*)d_in[18];
    float* out      = (float*)d_out;
    float* attn_out = out + (long long)NB*SS*VV;

    float *bqkv;
    GETSYM(bqkv,g_bqkv);
    f16 *sh16,*zh,*zl,*z1h,*z1l,*qkvh,*qkvl,*fh,*och,*ocl,*ph,*vth;
    GETSYM(sh16,g_sh);
    GETSYM(zh,g_zh); GETSYM(zl,g_zl); GETSYM(z1h,g_z1h); GETSYM(z1l,g_z1l);
    GETSYM(qkvh,g_qkvh); GETSYM(qkvl,g_qkvl); GETSYM(fh,g_fh);
    GETSYM(och,g_och); GETSYM(ocl,g_ocl); GETSYM(ph,g_ph); GETSYM(vth,g_vth);
    f16 *Wqkvh,*W1h,*W2h,*Wfh,*emh;
    GETSYM(Wqkvh,g_Wqkvh); GETSYM(W1h,g_W1h); GETSYM(W2h,g_W2h);
    GETSYM(Wfh,g_Wfh); GETSYM(emh,g_emh);

    const long long S3  = (long long)SS*H3;
    const long long SS2 = (long long)SS*SS;
    const long long SD  = (long long)SS*DHEAD;
    const int WN = LLAY*HH*HH;

    // ---- pack + round weights ----
    round_qkv_kernel<<<WN/1024,256>>>(Wq, Wqkvh, 0);
    round_qkv_kernel<<<WN/1024,256>>>(Wk, Wqkvh, 1);
    round_qkv_kernel<<<WN/1024,256>>>(Wv, Wqkvh, 2);
    bias_concat_kernel<<<LLAY*HH/256,256>>>(bq, bk, bv, bqkv);
    round_kernel<<<WN/1024,256>>>(W1, W1h, WN);
    round_kernel<<<WN/1024,256>>>(W2, W2h, WN);
    round_kernel<<<HH*HH/1024,256>>>(Wfc, Wfh, HH*HH);
    emb_round_pad_kernel<<<VPAD*HH/1024,256>>>(emb, emh);

    embed_kernel<<<NTOK,256>>>(x, emb, zh, zl);

    for (int l=0;l<LLAY;l++){
        const long long wo3 = (long long)l*H3*HH;
        const long long wo  = (long long)l*HH*HH;
        const bool last = (l==LLAY-1);

        // fused QKV: [8192,3072] = z @ Wqkv^T + bqkv; pairs only for last layer
        launch_tgemm(zh,zl, Wqkvh+wo3, bqkv+(long long)l*H3, nullptr,
                     qkvh, last?qkvl:nullptr,
                     NTOK,H3,HH, HH,HH,H3, 1.f,H3,false,1,0,0,nullptr, 1,1,0,0,0,0,0,0);

        // V -> Vt [bh][dh][S] from qkv slice
        {
            dim3 gr(SS/32, DHEAD/32, NB*NHEADS);
            transpose_v_f16<<<gr,256>>>(qkvh + 2*HH, vth);
        }

        // scores: Q@K^T/32 -> f16, compact causal grid + per-batch length skip
        launch_tgemm(qkvh, qkvl, qkvh+HH, nullptr, nullptr, sh16, nullptr,
                     SS,SS,DHEAD, H3,H3,SS, 1.0f/32.0f,SS,false, last?2:1, 1, 0, lengths,
                     NB*NHEADS, NHEADS, S3, DHEAD, S3, DHEAD,
                     (long long)NHEADS*SS2, SS2);

        attn_softmax_kernel<<<NB*NHEADS*SS,128>>>(sh16, lengths, ph,
                                                  last?attn_out:nullptr);

        // O = P @ Vt^T, triangular K skip (heavy-first tile order), out pairs
        launch_tgemm(ph,ph, vth, nullptr, nullptr, och, ocl,
                     SS,DHEAD,SS, SS,SS,DHEAD, 1.f,DHEAD,false,1,0,1,nullptr,
                     NB*NHEADS, 1, SS2, 0, SD, 0, SD, 0);

        add_ln_kernel<<<NTOK,256>>>(zh,zl, och,ocl, g1+l*HH, be1+l*HH, z1h, z1l);

        // FFN (A hi-only; FFN1 out hi-only)
        launch_tgemm(z1h,z1h, W1h+wo, b1+l*HH, nullptr, fh, nullptr,
                     NTOK,HH,HH, HH,HH,HH, 1.f,HH,true,1,0,0,nullptr, 1,1,0,0,0,0,0,0);
        launch_tgemm(fh,fh, W2h+wo, b2+l*HH, nullptr, och, ocl,
                     NTOK,HH,HH, HH,HH,HH, 1.f,HH,false,1,0,0,nullptr, 1,1,0,0,0,0,0,0);

        add_ln_kernel<<<NTOK,256>>>(z1h,z1l, och,ocl, g2+l*HH, be2+l*HH, zh, zl);
    }

    // out_fc = z @ Wfc^T + bfc (A split) -> pairs
    launch_tgemm(zh,zl, Wfh, bfc, nullptr, och, ocl,
                 NTOK,HH,HH, HH,HH,HH, 1.f,HH,false,2,0,0,nullptr, 1,1,0,0,0,0,0,0);
    // logits = out_fc @ emb^T, A hi-only
    launch_tgemm(och,och, emh, nullptr, out, nullptr, nullptr,
                 NTOK,VPAD,HH, HH,HH,VV, 1.f,VV,false,1,0,0,nullptr, 1,1,0,0,0,0,0,0);
    vocab_softmax_kernel<<<NTOK,256>>>(out);
}